// round 9
// baseline (speedup 1.0000x reference)
#include <cuda_runtime.h>
#include <cuda_fp16.h>
#include <cstdint>
#include <math.h>

// Problem constants
#define B_   8
#define C_   512
#define N_   4096
#define G_   8
#define CPG  64
#define O3   1536
#define EPSV 1e-6f
#define QSCALE 0.04419417382415922f   // 512^-0.5

// ---------------------------------------------------------------------------
// PTX helpers
// ---------------------------------------------------------------------------
__device__ __forceinline__ uint32_t smem_u32(const void* p) {
    uint32_t a;
    asm("{ .reg .u64 t; cvta.to.shared.u64 t, %1; cvt.u32.u64 %0, t; }" : "=r"(a) : "l"(p));
    return a;
}
__device__ __forceinline__ void ldsm_x4(uint32_t (&r)[4], uint32_t addr) {
    asm volatile("ldmatrix.sync.aligned.m8n8.x4.shared.b16 {%0,%1,%2,%3}, [%4];"
        : "=r"(r[0]), "=r"(r[1]), "=r"(r[2]), "=r"(r[3]) : "r"(addr));
}
__device__ __forceinline__ void mma16816(float (&d)[4], const uint32_t (&a)[4],
                                         uint32_t b0, uint32_t b1) {
    asm volatile(
        "mma.sync.aligned.m16n8k16.row.col.f32.f16.f16.f32 "
        "{%0,%1,%2,%3}, {%4,%5,%6,%7}, {%8,%9}, {%0,%1,%2,%3};"
        : "+f"(d[0]), "+f"(d[1]), "+f"(d[2]), "+f"(d[3])
        : "r"(a[0]), "r"(a[1]), "r"(a[2]), "r"(a[3]), "r"(b0), "r"(b1));
}
// fp16-accumulator variant (chunk accumulation experiment)
__device__ __forceinline__ void mma16816h(uint32_t (&d)[2], const uint32_t (&a)[4],
                                          uint32_t b0, uint32_t b1) {
    asm volatile(
        "mma.sync.aligned.m16n8k16.row.col.f16.f16.f16.f16 "
        "{%0,%1}, {%2,%3,%4,%5}, {%6,%7}, {%0,%1};"
        : "+r"(d[0]), "+r"(d[1])
        : "r"(a[0]), "r"(a[1]), "r"(a[2]), "r"(a[3]), "r"(b0), "r"(b1));
}
#define CP_ASYNC16(dst, src) \
    asm volatile("cp.async.cg.shared.global [%0], [%1], 16;" :: "r"(dst), "l"(src))
#define CP_COMMIT() asm volatile("cp.async.commit_group;" ::: "memory")
#define CP_WAIT0()  asm volatile("cp.async.wait_group 0;" ::: "memory")
#define CP_WAIT1()  asm volatile("cp.async.wait_group 1;" ::: "memory")
#define CP_WAIT2()  asm volatile("cp.async.wait_group 2;" ::: "memory")

// ---------------------------------------------------------------------------
// Scratch
// ---------------------------------------------------------------------------
__device__ __half g_Wh[(size_t)B_ * O3 * C_];
__device__ float  g_biasb[B_ * O3];
__device__ float  g_mean[B_ * G_], g_rstd[B_ * G_];
__device__ float  g_ssum[B_ * G_], g_ssq[B_ * G_];
__device__ __half g_xTh[(size_t)B_ * N_ * C_];        // x token-major fp16
__device__ __half g_xh [(size_t)B_ * C_ * N_];        // x channel-major fp16
__device__ __half g_khl[(size_t)B_ * C_ * N_];        // k logits fp16
__device__ __half g_kh[(size_t)B_ * C_ * N_];         // softmaxed k fp16
__device__ __half g_kxh[(size_t)B_ * C_ * C_];        // k_sm @ x^T
__device__ __half g_ctxh[(size_t)B_ * C_ * C_];
__device__ __half g_Mh[(size_t)B_ * C_ * C_];
__device__ __half g_Eh[(size_t)B_ * C_ * C_];         // M @ Wq
__device__ __half g_wqTh[(size_t)B_ * C_ * C_];       // Wq transposed [c,o]
__device__ __half g_pwh[C_ * C_];
__device__ float  g_fb[B_ * C_];                      // final fused bias

// ---------------------------------------------------------------------------
// Reductions
// ---------------------------------------------------------------------------
__device__ __forceinline__ float warp_sum(float v) {
#pragma unroll
    for (int o = 16; o > 0; o >>= 1) v += __shfl_xor_sync(0xffffffffu, v, o);
    return v;
}
__device__ __forceinline__ float warp_max(float v) {
#pragma unroll
    for (int o = 16; o > 0; o >>= 1) v = fmaxf(v, __shfl_xor_sync(0xffffffffu, v, o));
    return v;
}
__device__ __forceinline__ float block_sum(float v, float* sh) {
    int tid = threadIdx.x, nw = blockDim.x >> 5;
    __syncthreads();
    v = warp_sum(v);
    if ((tid & 31) == 0) sh[tid >> 5] = v;
    __syncthreads();
    if (tid < 32) {
        float w = (tid < nw) ? sh[tid] : 0.f;
        w = warp_sum(w);
        if (tid == 0) sh[0] = w;
    }
    __syncthreads();
    return sh[0];
}
__device__ __forceinline__ float block_max(float v, float* sh) {
    int tid = threadIdx.x, nw = blockDim.x >> 5;
    __syncthreads();
    v = warp_max(v);
    if ((tid & 31) == 0) sh[tid >> 5] = v;
    __syncthreads();
    if (tid < 32) {
        float w = (tid < nw) ? sh[tid] : -3.402823466e38f;
        w = warp_max(w);
        if (tid == 0) sh[0] = w;
    }
    __syncthreads();
    return sh[0];
}

// ---------------------------------------------------------------------------
// fp32 -> fp16 convert (proj_w) + GN stats zero-init (block 0)
// ---------------------------------------------------------------------------
__global__ __launch_bounds__(256) void f2h_init_kernel(
    const float* __restrict__ in, __half* __restrict__ out, size_t n4) {
    if (blockIdx.x == 0 && threadIdx.x < B_ * G_) {
        g_ssum[threadIdx.x] = 0.f;
        g_ssq[threadIdx.x] = 0.f;
    }
    size_t i = (size_t)blockIdx.x * 256 + threadIdx.x;
    if (i >= n4) return;
    float4 v = ((const float4*)in)[i];
    __half2* o = (__half2*)(out + i * 4);
    o[0] = __halves2half2(__float2half_rn(v.x), __float2half_rn(v.y));
    o[1] = __halves2half2(__float2half_rn(v.z), __float2half_rn(v.w));
}

__global__ void stats_fin_kernel() {
    int i = threadIdx.x;
    if (i < B_ * G_) {
        const float inv = 1.f / (float)(CPG * N_);
        float m = g_ssum[i] * inv;
        g_mean[i] = m;
        g_rstd[i] = rsqrtf(g_ssq[i] * inv - m * m + EPSV);
    }
}

// ---------------------------------------------------------------------------
// Fused: x [C,N] fp32 -> xh (same layout fp16) + xT [N,C] fp16 + GN stats.
// grid (N/32, G, B), block 256.
// ---------------------------------------------------------------------------
__global__ __launch_bounds__(256) void tconv_gn_kernel(
    const float* __restrict__ in, __half* __restrict__ outT,
    __half* __restrict__ outCh) {
    __shared__ float t[64][33];
    __shared__ float sh[32];
    int b = blockIdx.z, g = blockIdx.y;
    int n0 = blockIdx.x * 32, c0 = g * 64;
    const float* ip = in + (size_t)b * C_ * N_;
    __half* chp = outCh + (size_t)b * C_ * N_;
    int tid = threadIdx.x;
    int q = tid & 7, r0 = tid >> 3;
    float s = 0.f, ss = 0.f;
#pragma unroll
    for (int pass = 0; pass < 2; ++pass) {
        int c = r0 + pass * 32;
        float4 v = *(const float4*)(ip + (size_t)(c0 + c) * N_ + n0 + q * 4);
        s += v.x + v.y + v.z + v.w;
        ss = fmaf(v.x, v.x, fmaf(v.y, v.y, fmaf(v.z, v.z, fmaf(v.w, v.w, ss))));
        __half2* hp = (__half2*)(chp + (size_t)(c0 + c) * N_ + n0 + q * 4);
        hp[0] = __halves2half2(__float2half_rn(v.x), __float2half_rn(v.y));
        hp[1] = __halves2half2(__float2half_rn(v.z), __float2half_rn(v.w));
        t[c][q * 4 + 0] = v.x; t[c][q * 4 + 1] = v.y;
        t[c][q * 4 + 2] = v.z; t[c][q * 4 + 3] = v.w;
    }
    float bs  = block_sum(s, sh);
    float bss = block_sum(ss, sh);
    if (tid == 0) {
        atomicAdd(&g_ssum[b * G_ + g], bs);
        atomicAdd(&g_ssq [b * G_ + g], bss);
    }
    __half* op = outT + (size_t)b * N_ * C_;
    int c2 = tid & 31;
    int nr = tid >> 5;
#pragma unroll
    for (int pass = 0; pass < 4; ++pass) {
        int n = nr + pass * 8;
        int c = c2 * 2;
        __half2 hv = __halves2half2(__float2half_rn(t[c][n]),
                                    __float2half_rn(t[c + 1][n]));
        *(__half2*)(op + (size_t)(n0 + n) * C_ + c0 + c) = hv;
    }
}

// ---------------------------------------------------------------------------
// Fold GN (+q scale) into qkv weights; one block per output row, loop batches.
// Also scatter-writes the q-slab transpose (wqT).
// ---------------------------------------------------------------------------
__global__ __launch_bounds__(128) void prep_w_kernel(
    const float* __restrict__ qkv_w, const float* __restrict__ qkv_b,
    const float* __restrict__ gn_scale, const float* __restrict__ gn_bias) {
    int o = blockIdx.x;                        // 0..O3-1
    float qs = (o < C_) ? QSCALE : 1.f;
    const float* wrow = qkv_w + (size_t)o * C_;
    int tid = threadIdx.x;
    float w[4], sc[4], bi[4];
#pragma unroll
    for (int i = 0; i < 4; ++i) {
        int c = tid + i * 128;
        w[i]  = wrow[c];
        sc[i] = gn_scale[c];
        bi[i] = gn_bias[c];
    }
    float qb = qkv_b[o];
    __shared__ float sh[32];
#pragma unroll
    for (int b = 0; b < B_; ++b) {
        float acc = 0.f;
        __half* wh = g_Wh + ((size_t)b * O3 + o) * C_;
#pragma unroll
        for (int i = 0; i < 4; ++i) {
            int c = tid + i * 128;
            int g = c >> 6;
            float rstd = g_rstd[b * G_ + g];
            float mean = g_mean[b * G_ + g];
            float a = rstd * sc[i];
            float d = bi[i] - mean * a;
            __half hv = __float2half_rn(w[i] * a * qs);
            wh[c] = hv;
            if (o < C_) g_wqTh[(size_t)b * C_ * C_ + (size_t)c * C_ + o] = hv;
            acc = fmaf(w[i], d, acc);
        }
        acc = block_sum(acc, sh);
        if (tid == 0) g_biasb[b * O3 + o] = qs * (qb + acc);
    }
}

// ---------------------------------------------------------------------------
// Row softmax: fp16 logits -> fp16 probabilities (fp32 math inside)
// ---------------------------------------------------------------------------
__global__ __launch_bounds__(256) void softmax_kernel(
    const __half* __restrict__ kl, __half* __restrict__ kh) {
    int row = blockIdx.x;
    const __half2* p = (const __half2*)(kl + (size_t)row * N_);
    __half2* o = (__half2*)(kh + (size_t)row * N_);
    const int tid = threadIdx.x;
    float2 v[8];
    float mx = -3.402823466e38f;
#pragma unroll
    for (int i = 0; i < 8; i++) {
        v[i] = __half22float2(p[tid + i * 256]);
        mx = fmaxf(mx, fmaxf(v[i].x, v[i].y));
    }
    __shared__ float sh[32];
    mx = block_max(mx, sh);
    float s = 0.f;
#pragma unroll
    for (int i = 0; i < 8; i++) {
        v[i].x = __expf(v[i].x - mx); v[i].y = __expf(v[i].y - mx);
        s += v[i].x + v[i].y;
    }
    s = block_sum(s, sh);
    float inv = 1.f / s;
#pragma unroll
    for (int i = 0; i < 8; i++) {
        o[tid + i * 256] = __halves2half2(__float2half_rn(v[i].x * inv),
                                          __float2half_rn(v[i].y * inv));
    }
}

// ---------------------------------------------------------------------------
// fb[b,o] = proj_b[o] + sum_d M[b,o,d] * bq_b[b,d]
// ---------------------------------------------------------------------------
__global__ __launch_bounds__(256) void fb_kernel(const float* __restrict__ proj_b) {
    int r = blockIdx.x * 8 + (threadIdx.x >> 5);
    int b = r / C_, o = r % C_;
    const __half* Mrow = g_Mh + ((size_t)b * C_ + o) * C_;
    const float* bq = g_biasb + b * O3;
    int lane = threadIdx.x & 31;
    float s = 0.f;
    for (int d = lane; d < C_; d += 32)
        s += __half2float(Mrow[d]) * bq[d];
    s = warp_sum(s);
    if (lane == 0) g_fb[r] = s + proj_b[o];
}

// ---------------------------------------------------------------------------
// Shared GEMM plumbing
// ---------------------------------------------------------------------------
#define LDS_   40
#define NSTG   4

// ---- 128x128 tile kernel (fp32 accum) ------------------------------------
#define T_SZ   (128 * LDS_ * 2)
#define STAGE  (2 * T_SZ)
#define SMEMB  (NSTG * STAGE)

__device__ __forceinline__ void ld_tile_async128(
    const __half* __restrict__ g, int ldk, uint32_t sbase, int tid) {
#pragma unroll
    for (int i = 0; i < 4; ++i) {
        int idx = tid + i * 128;
        int row = idx >> 2, ch = idx & 3;
        CP_ASYNC16(sbase + row * (LDS_ * 2) + ch * 16,
                   g + (size_t)row * ldk + ch * 8);
    }
}

__global__ __launch_bounds__(128) void hmma_nt_kernel(
    const __half* __restrict__ A, int lda, size_t sA,
    const __half* __restrict__ Bs, int ldb, size_t sB,
    float* __restrict__ Cf, __half* __restrict__ Ch, int ldc, size_t sC,
    const float* __restrict__ bias, int bias_mode, int sBias,
    const float* __restrict__ resid, size_t sR,
    int K) {
    extern __shared__ char smem[];
    const uint32_t sb = smem_u32(smem);
    const int tid = threadIdx.x;
    const int wid = tid >> 5, lane = tid & 31;
    const int wm = wid & 1, wn = wid >> 1;
    const int bz = blockIdx.z;
    const int m0 = blockIdx.y * 128, n0 = blockIdx.x * 128;

    const __half* gA = A  + (size_t)bz * sA + (size_t)m0 * lda;
    const __half* gB = Bs + (size_t)bz * sB + (size_t)n0 * ldb;

    float acc[4][8][4] = {};
    const int nt = K >> 5;
#pragma unroll
    for (int s = 0; s < NSTG - 1; ++s) {
        if (s < nt) {
            uint32_t st = sb + s * STAGE;
            ld_tile_async128(gA + (s << 5), lda, st,        tid);
            ld_tile_async128(gB + (s << 5), ldb, st + T_SZ, tid);
        }
        CP_COMMIT();
    }

    const int a_m  = wm * 64 + (lane & 15);
    const int a_k  = (lane >> 4) * 8;
    const int b_nr = wn * 64 + (lane & 7) + ((lane >> 4) << 3);
    const int b_k  = ((lane >> 3) & 1) * 8;

    for (int kt = 0; kt < nt; ++kt) {
        const int pre = kt + NSTG - 1;
        if (pre < nt) {
            uint32_t st = sb + (pre & (NSTG - 1)) * STAGE;
            ld_tile_async128(gA + (pre << 5), lda, st,        tid);
            ld_tile_async128(gB + (pre << 5), ldb, st + T_SZ, tid);
        }
        CP_COMMIT();
        const int rem = nt - 1 - kt;
        if (rem >= NSTG - 2) { CP_WAIT2(); }
        else if (rem == 1)   { CP_WAIT1(); }
        else                 { CP_WAIT0(); }
        __syncthreads();

        const uint32_t st = sb + (kt & (NSTG - 1)) * STAGE;
#pragma unroll
        for (int ks = 0; ks < 2; ++ks) {
            const int kk = ks * 16;
            uint32_t ah[4][4], bb[4][4];
#pragma unroll
            for (int mi = 0; mi < 4; ++mi)
                ldsm_x4(ah[mi], st + (a_m + mi * 16) * (LDS_ * 2) + (kk + a_k) * 2);
#pragma unroll
            for (int nj = 0; nj < 4; ++nj)
                ldsm_x4(bb[nj], st + T_SZ + (b_nr + nj * 16) * (LDS_ * 2) + (kk + b_k) * 2);
#pragma unroll
            for (int mi = 0; mi < 4; ++mi)
#pragma unroll
                for (int nj = 0; nj < 4; ++nj) {
                    mma16816(acc[mi][2 * nj],     ah[mi], bb[nj][0], bb[nj][1]);
                    mma16816(acc[mi][2 * nj + 1], ah[mi], bb[nj][2], bb[nj][3]);
                }
        }
        __syncthreads();
    }

    const int r_in = lane >> 2;
    const int c_in = (lane & 3) * 2;
    const float* bp = bias ? bias + bz * sBias : nullptr;
#pragma unroll
    for (int mi = 0; mi < 4; ++mi) {
        int row0 = m0 + wm * 64 + mi * 16 + r_in;
        int row1 = row0 + 8;
        float rb0 = 0.f, rb1 = 0.f;
        if (bias_mode == 1) { rb0 = bp[row0]; rb1 = bp[row1]; }
#pragma unroll
        for (int ni = 0; ni < 8; ++ni) {
            int col = n0 + wn * 64 + ni * 8 + c_in;
            float cb0 = 0.f, cb1 = 0.f;
            if (bias_mode == 2) { cb0 = bp[col]; cb1 = bp[col + 1]; }
            float v00 = acc[mi][ni][0] + rb0 + cb0;
            float v01 = acc[mi][ni][1] + rb0 + cb1;
            float v10 = acc[mi][ni][2] + rb1 + cb0;
            float v11 = acc[mi][ni][3] + rb1 + cb1;
            if (Cf) {
                float* Cb = Cf + (size_t)bz * sC;
                if (resid) {
                    const float* Rb = resid + (size_t)bz * sR;
                    float2 r0 = *(const float2*)(Rb + (size_t)row0 * ldc + col);
                    float2 r1 = *(const float2*)(Rb + (size_t)row1 * ldc + col);
                    v00 += r0.x; v01 += r0.y; v10 += r1.x; v11 += r1.y;
                }
                *(float2*)(Cb + (size_t)row0 * ldc + col) = make_float2(v00, v01);
                *(float2*)(Cb + (size_t)row1 * ldc + col) = make_float2(v10, v11);
            } else {
                __half* Hb = Ch + (size_t)bz * sC;
                *(__half2*)(Hb + (size_t)row0 * ldc + col) =
                    __halves2half2(__float2half_rn(v00), __float2half_rn(v01));
                *(__half2*)(Hb + (size_t)row1 * ldc + col) =
                    __halves2half2(__float2half_rn(v10), __float2half_rn(v11));
            }
        }
    }
}

// ---- 64x64 tile kernel: fp16 chunk accumulation experiment ----------------
#define T64_SZ  (64 * LDS_ * 2)
#define STAGE64 (2 * T64_SZ)
#define SMEMB64 (NSTG * STAGE64)

__device__ __forceinline__ void ld_tile_async64(
    const __half* __restrict__ g, int ldk, uint32_t sbase, int tid) {
#pragma unroll
    for (int i = 0; i < 2; ++i) {
        int idx = tid + i * 128;
        int row = idx >> 2, ch = idx & 3;
        CP_ASYNC16(sbase + row * (LDS_ * 2) + ch * 16,
                   g + (size_t)row * ldk + ch * 8);
    }
}

__global__ __launch_bounds__(128) void hmma_nt64_kernel(
    const __half* __restrict__ A, int lda, size_t sA,
    const __half* __restrict__ Bs, int ldb, size_t sB,
    __half* __restrict__ Ch, int ldc, size_t sC,
    const float* __restrict__ bias, int bias_mode, int sBias,
    int K) {
    extern __shared__ char smem[];
    const uint32_t sb = smem_u32(smem);
    const int tid = threadIdx.x;
    const int wid = tid >> 5, lane = tid & 31;
    const int wm = wid & 1, wn = wid >> 1;
    const int bz = blockIdx.z;
    const int m0 = blockIdx.y * 64, n0 = blockIdx.x * 64;

    const __half* gA = A  + (size_t)bz * sA + (size_t)m0 * lda;
    const __half* gB = Bs + (size_t)bz * sB + (size_t)n0 * ldb;

    float acc[2][4][4] = {};
    const int nt = K >> 5;
#pragma unroll
    for (int s = 0; s < NSTG - 1; ++s) {
        if (s < nt) {
            uint32_t st = sb + s * STAGE64;
            ld_tile_async64(gA + (s << 5), lda, st,          tid);
            ld_tile_async64(gB + (s << 5), ldb, st + T64_SZ, tid);
        }
        CP_COMMIT();
    }

    const int a_m  = wm * 32 + (lane & 15);
    const int a_k  = (lane >> 4) * 8;
    const int b_nr = wn * 32 + (lane & 7) + ((lane >> 4) << 3);
    const int b_k  = ((lane >> 3) & 1) * 8;

    for (int kt = 0; kt < nt; ++kt) {
        const int pre = kt + NSTG - 1;
        if (pre < nt) {
            uint32_t st = sb + (pre & (NSTG - 1)) * STAGE64;
            ld_tile_async64(gA + (pre << 5), lda, st,          tid);
            ld_tile_async64(gB + (pre << 5), ldb, st + T64_SZ, tid);
        }
        CP_COMMIT();
        const int rem = nt - 1 - kt;
        if (rem >= NSTG - 2) { CP_WAIT2(); }
        else if (rem == 1)   { CP_WAIT1(); }
        else                 { CP_WAIT0(); }
        __syncthreads();

        const uint32_t st = sb + (kt & (NSTG - 1)) * STAGE64;
        // fp16 chunk accumulators for this K=32 tile
        uint32_t hacc[2][4][2] = {};
#pragma unroll
        for (int ks = 0; ks < 2; ++ks) {
            const int kk = ks * 16;
            uint32_t ah[2][4], bb[2][4];
#pragma unroll
            for (int mi = 0; mi < 2; ++mi)
                ldsm_x4(ah[mi], st + (a_m + mi * 16) * (LDS_ * 2) + (kk + a_k) * 2);
#pragma unroll
            for (int nj = 0; nj < 2; ++nj)
                ldsm_x4(bb[nj], st + T64_SZ + (b_nr + nj * 16) * (LDS_ * 2) + (kk + b_k) * 2);
#pragma unroll
            for (int mi = 0; mi < 2; ++mi)
#pragma unroll
                for (int nj = 0; nj < 2; ++nj) {
                    mma16816h(hacc[mi][2 * nj],     ah[mi], bb[nj][0], bb[nj][1]);
                    mma16816h(hacc[mi][2 * nj + 1], ah[mi], bb[nj][2], bb[nj][3]);
                }
        }
        // fold fp16 chunk into fp32 accumulators
#pragma unroll
        for (int mi = 0; mi < 2; ++mi)
#pragma unroll
            for (int ni = 0; ni < 4; ++ni) {
                float2 lo = __half22float2(*(__half2*)&hacc[mi][ni][0]);
                float2 hi = __half22float2(*(__half2*)&hacc[mi][ni][1]);
                acc[mi][ni][0] += lo.x; acc[mi][ni][1] += lo.y;
                acc[mi][ni][2] += hi.x; acc[mi][ni][3] += hi.y;
            }
        __syncthreads();
    }

    const int r_in = lane >> 2;
    const int c_in = (lane & 3) * 2;
    const float* bp = bias ? bias + bz * sBias : nullptr;
    __half* Hb = Ch + (size_t)bz * sC;
#pragma unroll
    for (int mi = 0; mi < 2; ++mi) {
        int row0 = m0 + wm * 32 + mi * 16 + r_in;
        int row1 = row0 + 8;
        float rb0 = 0.f, rb1 = 0.f;
        if (bias_mode == 1) { rb0 = bp[row0]; rb1 = bp[row1]; }
#pragma unroll
        for (int ni = 0; ni < 4; ++ni) {
            int col = n0 + wn * 32 + ni * 8 + c_in;
            float cb0 = 0.f, cb1 = 0.f;
            if (bias_mode == 2) { cb0 = bp[col]; cb1 = bp[col + 1]; }
            float v00 = acc[mi][ni][0] + rb0 + cb0;
            float v01 = acc[mi][ni][1] + rb0 + cb1;
            float v10 = acc[mi][ni][2] + rb1 + cb0;
            float v11 = acc[mi][ni][3] + rb1 + cb1;
            *(__half2*)(Hb + (size_t)row0 * ldc + col) =
                __halves2half2(__float2half_rn(v00), __float2half_rn(v01));
            *(__half2*)(Hb + (size_t)row1 * ldc + col) =
                __halves2half2(__float2half_rn(v10), __float2half_rn(v11));
        }
    }
}

// ---------------------------------------------------------------------------
// Launch sequence
// ---------------------------------------------------------------------------
extern "C" void kernel_launch(void* const* d_in, const int* in_sizes, int n_in,
                              void* d_out, int out_size) {
    const float* x        = (const float*)d_in[0];
    const float* qkv_w    = (const float*)d_in[1];
    const float* qkv_b    = (const float*)d_in[2];
    const float* proj_w   = (const float*)d_in[3];
    const float* proj_b   = (const float*)d_in[4];
    const float* gn_scale = (const float*)d_in[5];
    const float* gn_bias  = (const float*)d_in[6];
    float* out = (float*)d_out;

    cudaFuncSetAttribute(hmma_nt_kernel, cudaFuncAttributeMaxDynamicSharedMemorySize, SMEMB);
    cudaFuncSetAttribute(hmma_nt64_kernel, cudaFuncAttributeMaxDynamicSharedMemorySize, SMEMB64);

    float *biasb, *fb;
    __half *Wh, *xTh, *xh, *khl, *kh, *kxh, *ctxh, *Mh, *Eh, *wqTh, *pwh;
    cudaGetSymbolAddress((void**)&biasb, g_biasb);
    cudaGetSymbolAddress((void**)&fb, g_fb);
    cudaGetSymbolAddress((void**)&Wh, g_Wh);
    cudaGetSymbolAddress((void**)&xTh, g_xTh);
    cudaGetSymbolAddress((void**)&xh, g_xh);
    cudaGetSymbolAddress((void**)&khl, g_khl);
    cudaGetSymbolAddress((void**)&kh, g_kh);
    cudaGetSymbolAddress((void**)&kxh, g_kxh);
    cudaGetSymbolAddress((void**)&ctxh, g_ctxh);
    cudaGetSymbolAddress((void**)&Mh, g_Mh);
    cudaGetSymbolAddress((void**)&Eh, g_Eh);
    cudaGetSymbolAddress((void**)&wqTh, g_wqTh);
    cudaGetSymbolAddress((void**)&pwh, g_pwh);

    // 1) proj_w convert (+stats zero), fused x convert/transpose/stats, fold
    f2h_init_kernel<<<(C_ * C_ / 4 + 255) / 256, 256>>>(proj_w, pwh, C_ * C_ / 4);
    tconv_gn_kernel<<<dim3(N_ / 32, G_, B_), 256>>>(x, xTh, xh);
    stats_fin_kernel<<<1, 64>>>();
    prep_w_kernel<<<O3, 128>>>(qkv_w, qkv_b, gn_scale, gn_bias);
    // 2) k logits (fp16 out): k[d,n] = Wk . xT + bk
    hmma_nt_kernel<<<dim3(N_ / 128, C_ / 128, B_), 128, SMEMB>>>(
        Wh + (size_t)C_ * C_, C_, (size_t)O3 * C_,
        xTh, C_, (size_t)N_ * C_,
        nullptr, khl, N_, (size_t)C_ * N_,
        biasb + C_, 1, O3, nullptr, 0, C_);
    // 3) softmax over tokens
    softmax_kernel<<<B_ * C_, 256>>>(khl, kh);
    // 4) kx[d,c] = k_sm . x^T   (K=4096)
    hmma_nt64_kernel<<<dim3(C_ / 64, C_ / 64, B_), 128, SMEMB64>>>(
        kh, N_, (size_t)C_ * N_,
        xh, N_, (size_t)C_ * N_,
        kxh, C_, (size_t)C_ * C_,
        nullptr, 0, 0, N_);
    // 5) ctx[d,e] = kx . Wv^T + bv[e]
    hmma_nt64_kernel<<<dim3(C_ / 64, C_ / 64, B_), 128, SMEMB64>>>(
        kxh, C_, (size_t)C_ * C_,
        Wh + (size_t)2 * C_ * C_, C_, (size_t)O3 * C_,
        ctxh, C_, (size_t)C_ * C_,
        biasb + 2 * C_, 2, O3, C_);
    // 6) M[o,d] = proj_w . ctx^T
    hmma_nt64_kernel<<<dim3(C_ / 64, C_ / 64, B_), 128, SMEMB64>>>(
        pwh, C_, 0,
        ctxh, C_, (size_t)C_ * C_,
        Mh, C_, (size_t)C_ * C_,
        nullptr, 0, 0, C_);
    // 7) E[o,c] = M . WqT^T  (= M @ Wq)
    hmma_nt64_kernel<<<dim3(C_ / 64, C_ / 64, B_), 128, SMEMB64>>>(
        Mh, C_, (size_t)C_ * C_,
        wqTh, C_, (size_t)C_ * C_,
        Eh, C_, (size_t)C_ * C_,
        nullptr, 0, 0, C_);
    // 8) fb = proj_b + M @ bq
    fb_kernel<<<B_ * C_ / 8, 256>>>(proj_b);
    // 9) out[o,n] = E . xT^T + fb[o] + x
    hmma_nt_kernel<<<dim3(N_ / 128, C_ / 128, B_), 128, SMEMB>>>(
        Eh, C_, (size_t)C_ * C_,
        xTh, C_, (size_t)N_ * C_,
        out, nullptr, N_, (size_t)C_ * N_,
        fb, 1, C_, x, (size_t)C_ * N_, C_);
}

// round 10
// speedup vs baseline: 1.0661x; 1.0661x over previous
#include <cuda_runtime.h>
#include <cuda_fp16.h>
#include <cstdint>
#include <math.h>

// Problem constants
#define B_   8
#define C_   512
#define N_   4096
#define G_   8
#define CPG  64
#define O3   1536
#define EPSV 1e-6f
#define QSCALE 0.04419417382415922f   // 512^-0.5

// ---------------------------------------------------------------------------
// PTX helpers
// ---------------------------------------------------------------------------
__device__ __forceinline__ uint32_t smem_u32(const void* p) {
    uint32_t a;
    asm("{ .reg .u64 t; cvta.to.shared.u64 t, %1; cvt.u32.u64 %0, t; }" : "=r"(a) : "l"(p));
    return a;
}
__device__ __forceinline__ void ldsm_x4(uint32_t (&r)[4], uint32_t addr) {
    asm volatile("ldmatrix.sync.aligned.m8n8.x4.shared.b16 {%0,%1,%2,%3}, [%4];"
        : "=r"(r[0]), "=r"(r[1]), "=r"(r[2]), "=r"(r[3]) : "r"(addr));
}
__device__ __forceinline__ void mma16816(float (&d)[4], const uint32_t (&a)[4],
                                         uint32_t b0, uint32_t b1) {
    asm volatile(
        "mma.sync.aligned.m16n8k16.row.col.f32.f16.f16.f32 "
        "{%0,%1,%2,%3}, {%4,%5,%6,%7}, {%8,%9}, {%0,%1,%2,%3};"
        : "+f"(d[0]), "+f"(d[1]), "+f"(d[2]), "+f"(d[3])
        : "r"(a[0]), "r"(a[1]), "r"(a[2]), "r"(a[3]), "r"(b0), "r"(b1));
}
#define CP_ASYNC16(dst, src) \
    asm volatile("cp.async.cg.shared.global [%0], [%1], 16;" :: "r"(dst), "l"(src))
#define CP_COMMIT() asm volatile("cp.async.commit_group;" ::: "memory")
#define CP_WAIT0()  asm volatile("cp.async.wait_group 0;" ::: "memory")
#define CP_WAIT1()  asm volatile("cp.async.wait_group 1;" ::: "memory")
#define CP_WAIT2()  asm volatile("cp.async.wait_group 2;" ::: "memory")

// ---------------------------------------------------------------------------
// Scratch
// ---------------------------------------------------------------------------
__device__ __half g_Wh[(size_t)B_ * O3 * C_];
__device__ float  g_biasb[B_ * O3];
__device__ float  g_ssum[B_ * G_], g_ssq[B_ * G_];
__device__ __half g_xTh[(size_t)B_ * N_ * C_];        // x token-major fp16
__device__ __half g_xh [(size_t)B_ * C_ * N_];        // x channel-major fp16
__device__ __half g_khl[(size_t)B_ * C_ * N_];        // k logits fp16
__device__ __half g_kh[(size_t)B_ * C_ * N_];         // softmaxed k fp16
__device__ __half g_kxh[(size_t)B_ * C_ * C_];        // k_sm @ x^T
__device__ __half g_ctxh[(size_t)B_ * C_ * C_];
__device__ __half g_Mh[(size_t)B_ * C_ * C_];
__device__ __half g_Eh[(size_t)B_ * C_ * C_];         // M @ Wq
__device__ __half g_wqTh[(size_t)B_ * C_ * C_];       // Wq transposed [c,o]
__device__ __half g_pwh[C_ * C_];
__device__ float  g_fb[B_ * C_];                      // final fused bias

// ---------------------------------------------------------------------------
// Reductions
// ---------------------------------------------------------------------------
__device__ __forceinline__ float warp_sum(float v) {
#pragma unroll
    for (int o = 16; o > 0; o >>= 1) v += __shfl_xor_sync(0xffffffffu, v, o);
    return v;
}
__device__ __forceinline__ float warp_max(float v) {
#pragma unroll
    for (int o = 16; o > 0; o >>= 1) v = fmaxf(v, __shfl_xor_sync(0xffffffffu, v, o));
    return v;
}
__device__ __forceinline__ float block_sum(float v, float* sh) {
    int tid = threadIdx.x, nw = blockDim.x >> 5;
    __syncthreads();
    v = warp_sum(v);
    if ((tid & 31) == 0) sh[tid >> 5] = v;
    __syncthreads();
    if (tid < 32) {
        float w = (tid < nw) ? sh[tid] : 0.f;
        w = warp_sum(w);
        if (tid == 0) sh[0] = w;
    }
    __syncthreads();
    return sh[0];
}
__device__ __forceinline__ float block_max(float v, float* sh) {
    int tid = threadIdx.x, nw = blockDim.x >> 5;
    __syncthreads();
    v = warp_max(v);
    if ((tid & 31) == 0) sh[tid >> 5] = v;
    __syncthreads();
    if (tid < 32) {
        float w = (tid < nw) ? sh[tid] : -3.402823466e38f;
        w = warp_max(w);
        if (tid == 0) sh[0] = w;
    }
    __syncthreads();
    return sh[0];
}

// GN stats -> (mean, rstd) on the fly
__device__ __forceinline__ void gn_ms(int bg, float* mean, float* rstd) {
    const float inv = 1.f / (float)(CPG * N_);
    float m = g_ssum[bg] * inv;
    *mean = m;
    *rstd = rsqrtf(g_ssq[bg] * inv - m * m + EPSV);
}

// ---------------------------------------------------------------------------
// fp32 -> fp16 convert (proj_w) + GN stats zero-init (block 0)
// ---------------------------------------------------------------------------
__global__ __launch_bounds__(256) void f2h_init_kernel(
    const float* __restrict__ in, __half* __restrict__ out, size_t n4) {
    if (blockIdx.x == 0 && threadIdx.x < B_ * G_) {
        g_ssum[threadIdx.x] = 0.f;
        g_ssq[threadIdx.x] = 0.f;
    }
    size_t i = (size_t)blockIdx.x * 256 + threadIdx.x;
    if (i >= n4) return;
    float4 v = ((const float4*)in)[i];
    __half2* o = (__half2*)(out + i * 4);
    o[0] = __halves2half2(__float2half_rn(v.x), __float2half_rn(v.y));
    o[1] = __halves2half2(__float2half_rn(v.z), __float2half_rn(v.w));
}

// ---------------------------------------------------------------------------
// Fused: x [C,N] fp32 -> xh (same layout fp16) + xT [N,C] fp16 + GN stats.
// grid (N/32, G, B), block 256.
// ---------------------------------------------------------------------------
__global__ __launch_bounds__(256) void tconv_gn_kernel(
    const float* __restrict__ in, __half* __restrict__ outT,
    __half* __restrict__ outCh) {
    __shared__ float t[64][33];
    __shared__ float sh[32];
    int b = blockIdx.z, g = blockIdx.y;
    int n0 = blockIdx.x * 32, c0 = g * 64;
    const float* ip = in + (size_t)b * C_ * N_;
    __half* chp = outCh + (size_t)b * C_ * N_;
    int tid = threadIdx.x;
    int q = tid & 7, r0 = tid >> 3;
    float s = 0.f, ss = 0.f;
#pragma unroll
    for (int pass = 0; pass < 2; ++pass) {
        int c = r0 + pass * 32;
        float4 v = *(const float4*)(ip + (size_t)(c0 + c) * N_ + n0 + q * 4);
        s += v.x + v.y + v.z + v.w;
        ss = fmaf(v.x, v.x, fmaf(v.y, v.y, fmaf(v.z, v.z, fmaf(v.w, v.w, ss))));
        __half2* hp = (__half2*)(chp + (size_t)(c0 + c) * N_ + n0 + q * 4);
        hp[0] = __halves2half2(__float2half_rn(v.x), __float2half_rn(v.y));
        hp[1] = __halves2half2(__float2half_rn(v.z), __float2half_rn(v.w));
        t[c][q * 4 + 0] = v.x; t[c][q * 4 + 1] = v.y;
        t[c][q * 4 + 2] = v.z; t[c][q * 4 + 3] = v.w;
    }
    float bs  = block_sum(s, sh);
    float bss = block_sum(ss, sh);
    if (tid == 0) {
        atomicAdd(&g_ssum[b * G_ + g], bs);
        atomicAdd(&g_ssq [b * G_ + g], bss);
    }
    // transpose out: each thread writes 4 consecutive c (8 B) per pass
    __half* op = outT + (size_t)b * N_ * C_;
    int c4 = (tid & 15) * 4;
    int nr = tid >> 4;                        // 16 n-rows per pass
#pragma unroll
    for (int pass = 0; pass < 2; ++pass) {
        int n = nr + pass * 16;
        __half2 vv[2];
        vv[0] = __halves2half2(__float2half_rn(t[c4 + 0][n]),
                               __float2half_rn(t[c4 + 1][n]));
        vv[1] = __halves2half2(__float2half_rn(t[c4 + 2][n]),
                               __float2half_rn(t[c4 + 3][n]));
        *(uint2*)(op + (size_t)(n0 + n) * C_ + c0 + c4) = *(uint2*)vv;
    }
}

// ---------------------------------------------------------------------------
// Fold GN (+q scale) into qkv weights -> fp16; fold means into bias (fp32)
// grid B_*O3, block 128 (round-8 proven shape). Stats finalized inline.
// ---------------------------------------------------------------------------
__global__ __launch_bounds__(128) void prep_w_kernel(
    const float* __restrict__ qkv_w, const float* __restrict__ qkv_b,
    const float* __restrict__ gn_scale, const float* __restrict__ gn_bias) {
    int bo = blockIdx.x;
    int b = bo / O3, o = bo % O3;
    float qs = (o < C_) ? QSCALE : 1.f;
    const float* wrow = qkv_w + (size_t)o * C_;
    __half* wh = g_Wh + (size_t)bo * C_;
    float acc = 0.f;
#pragma unroll
    for (int i = 0; i < 4; ++i) {
        int c = threadIdx.x + i * 128;
        float mean, rstd;
        gn_ms(b * G_ + (c >> 6), &mean, &rstd);
        float a = rstd * gn_scale[c];
        float d = gn_bias[c] - mean * a;
        float w = wrow[c];
        wh[c] = __float2half_rn(w * a * qs);
        acc = fmaf(w, d, acc);
    }
    __shared__ float sh[32];
    acc = block_sum(acc, sh);
    if (threadIdx.x == 0) g_biasb[bo] = qs * (qkv_b[o] + acc);
}

// ---------------------------------------------------------------------------
// Transpose q-slab of folded weights: Wq [o,c] -> wqT [c,o]  (fp16, per batch)
// ---------------------------------------------------------------------------
__global__ __launch_bounds__(256) void wqt_kernel() {
    __shared__ __half t[32][33];
    int b = blockIdx.z;
    const __half* W = g_Wh + (size_t)b * O3 * C_;
    __half* outp = g_wqTh + (size_t)b * C_ * C_;
    int c0 = blockIdx.x * 32, o0 = blockIdx.y * 32;
    int tx = threadIdx.x, ty = threadIdx.y;
    for (int j = ty; j < 32; j += 8)
        t[j][tx] = W[(size_t)(o0 + j) * C_ + c0 + tx];
    __syncthreads();
    for (int j = ty; j < 32; j += 8)
        outp[(size_t)(c0 + j) * C_ + o0 + tx] = t[tx][j];
}

// ---------------------------------------------------------------------------
// Row softmax: fp16 logits -> fp16 probabilities (fp32 math inside)
// ---------------------------------------------------------------------------
__global__ __launch_bounds__(256) void softmax_kernel(
    const __half* __restrict__ kl, __half* __restrict__ kh) {
    int row = blockIdx.x;
    const __half2* p = (const __half2*)(kl + (size_t)row * N_);
    __half2* o = (__half2*)(kh + (size_t)row * N_);
    const int tid = threadIdx.x;
    float2 v[8];
    float mx = -3.402823466e38f;
#pragma unroll
    for (int i = 0; i < 8; i++) {
        v[i] = __half22float2(p[tid + i * 256]);
        mx = fmaxf(mx, fmaxf(v[i].x, v[i].y));
    }
    __shared__ float sh[32];
    mx = block_max(mx, sh);
    float s = 0.f;
#pragma unroll
    for (int i = 0; i < 8; i++) {
        v[i].x = __expf(v[i].x - mx); v[i].y = __expf(v[i].y - mx);
        s += v[i].x + v[i].y;
    }
    s = block_sum(s, sh);
    float inv = 1.f / s;
#pragma unroll
    for (int i = 0; i < 8; i++) {
        o[tid + i * 256] = __halves2half2(__float2half_rn(v[i].x * inv),
                                          __float2half_rn(v[i].y * inv));
    }
}

// ---------------------------------------------------------------------------
// fb[b,o] = proj_b[o] + sum_d M[b,o,d] * bq_b[b,d]
// ---------------------------------------------------------------------------
__global__ __launch_bounds__(256) void fb_kernel(const float* __restrict__ proj_b) {
    int r = blockIdx.x * 8 + (threadIdx.x >> 5);
    int b = r / C_, o = r % C_;
    const __half* Mrow = g_Mh + ((size_t)b * C_ + o) * C_;
    const float* bq = g_biasb + b * O3;
    int lane = threadIdx.x & 31;
    float s = 0.f;
    for (int d = lane; d < C_; d += 32)
        s += __half2float(Mrow[d]) * bq[d];
    s = warp_sum(s);
    if (lane == 0) g_fb[r] = s + proj_b[o];
}

// ---------------------------------------------------------------------------
// Shared GEMM plumbing
// ---------------------------------------------------------------------------
#define LDS_   40
#define NSTG   4

// ---- 128x128 tile kernel -------------------------------------------------
#define T_SZ   (128 * LDS_ * 2)
#define STAGE  (2 * T_SZ)
#define SMEMB  (NSTG * STAGE)

__device__ __forceinline__ void ld_tile_async128(
    const __half* __restrict__ g, int ldk, uint32_t sbase, int tid) {
#pragma unroll
    for (int i = 0; i < 4; ++i) {
        int idx = tid + i * 128;
        int row = idx >> 2, ch = idx & 3;
        CP_ASYNC16(sbase + row * (LDS_ * 2) + ch * 16,
                   g + (size_t)row * ldk + ch * 8);
    }
}

__global__ __launch_bounds__(128) void hmma_nt_kernel(
    const __half* __restrict__ A, int lda, size_t sA,
    const __half* __restrict__ Bs, int ldb, size_t sB,
    float* __restrict__ Cf, __half* __restrict__ Ch, int ldc, size_t sC,
    const float* __restrict__ bias, int bias_mode, int sBias,
    const float* __restrict__ resid, size_t sR,
    int K) {
    extern __shared__ char smem[];
    const uint32_t sb = smem_u32(smem);
    const int tid = threadIdx.x;
    const int wid = tid >> 5, lane = tid & 31;
    const int wm = wid & 1, wn = wid >> 1;
    const int bz = blockIdx.z;
    const int m0 = blockIdx.y * 128, n0 = blockIdx.x * 128;

    const __half* gA = A  + (size_t)bz * sA + (size_t)m0 * lda;
    const __half* gB = Bs + (size_t)bz * sB + (size_t)n0 * ldb;

    float acc[4][8][4] = {};
    const int nt = K >> 5;
#pragma unroll
    for (int s = 0; s < NSTG - 1; ++s) {
        if (s < nt) {
            uint32_t st = sb + s * STAGE;
            ld_tile_async128(gA + (s << 5), lda, st,        tid);
            ld_tile_async128(gB + (s << 5), ldb, st + T_SZ, tid);
        }
        CP_COMMIT();
    }

    const int a_m  = wm * 64 + (lane & 15);
    const int a_k  = (lane >> 4) * 8;
    const int b_nr = wn * 64 + (lane & 7) + ((lane >> 4) << 3);
    const int b_k  = ((lane >> 3) & 1) * 8;

    for (int kt = 0; kt < nt; ++kt) {
        const int pre = kt + NSTG - 1;
        if (pre < nt) {
            uint32_t st = sb + (pre & (NSTG - 1)) * STAGE;
            ld_tile_async128(gA + (pre << 5), lda, st,        tid);
            ld_tile_async128(gB + (pre << 5), ldb, st + T_SZ, tid);
        }
        CP_COMMIT();
        const int rem = nt - 1 - kt;
        if (rem >= NSTG - 2) { CP_WAIT2(); }
        else if (rem == 1)   { CP_WAIT1(); }
        else                 { CP_WAIT0(); }
        __syncthreads();

        const uint32_t st = sb + (kt & (NSTG - 1)) * STAGE;
#pragma unroll
        for (int ks = 0; ks < 2; ++ks) {
            const int kk = ks * 16;
            uint32_t ah[4][4], bb[4][4];
#pragma unroll
            for (int mi = 0; mi < 4; ++mi)
                ldsm_x4(ah[mi], st + (a_m + mi * 16) * (LDS_ * 2) + (kk + a_k) * 2);
#pragma unroll
            for (int nj = 0; nj < 4; ++nj)
                ldsm_x4(bb[nj], st + T_SZ + (b_nr + nj * 16) * (LDS_ * 2) + (kk + b_k) * 2);
#pragma unroll
            for (int mi = 0; mi < 4; ++mi)
#pragma unroll
                for (int nj = 0; nj < 4; ++nj) {
                    mma16816(acc[mi][2 * nj],     ah[mi], bb[nj][0], bb[nj][1]);
                    mma16816(acc[mi][2 * nj + 1], ah[mi], bb[nj][2], bb[nj][3]);
                }
        }
        __syncthreads();
    }

    const int r_in = lane >> 2;
    const int c_in = (lane & 3) * 2;
    const float* bp = bias ? bias + bz * sBias : nullptr;
#pragma unroll
    for (int mi = 0; mi < 4; ++mi) {
        int row0 = m0 + wm * 64 + mi * 16 + r_in;
        int row1 = row0 + 8;
        float rb0 = 0.f, rb1 = 0.f;
        if (bias_mode == 1) { rb0 = bp[row0]; rb1 = bp[row1]; }
#pragma unroll
        for (int ni = 0; ni < 8; ++ni) {
            int col = n0 + wn * 64 + ni * 8 + c_in;
            float cb0 = 0.f, cb1 = 0.f;
            if (bias_mode == 2) { cb0 = bp[col]; cb1 = bp[col + 1]; }
            float v00 = acc[mi][ni][0] + rb0 + cb0;
            float v01 = acc[mi][ni][1] + rb0 + cb1;
            float v10 = acc[mi][ni][2] + rb1 + cb0;
            float v11 = acc[mi][ni][3] + rb1 + cb1;
            if (Cf) {
                float* Cb = Cf + (size_t)bz * sC;
                if (resid) {
                    const float* Rb = resid + (size_t)bz * sR;
                    float2 r0 = *(const float2*)(Rb + (size_t)row0 * ldc + col);
                    float2 r1 = *(const float2*)(Rb + (size_t)row1 * ldc + col);
                    v00 += r0.x; v01 += r0.y; v10 += r1.x; v11 += r1.y;
                }
                *(float2*)(Cb + (size_t)row0 * ldc + col) = make_float2(v00, v01);
                *(float2*)(Cb + (size_t)row1 * ldc + col) = make_float2(v10, v11);
            } else {
                __half* Hb = Ch + (size_t)bz * sC;
                *(__half2*)(Hb + (size_t)row0 * ldc + col) =
                    __halves2half2(__float2half_rn(v00), __float2half_rn(v01));
                *(__half2*)(Hb + (size_t)row1 * ldc + col) =
                    __halves2half2(__float2half_rn(v10), __float2half_rn(v11));
            }
        }
    }
}

// ---- 64x64 tile kernel (fp32 accum; for M=N=512 GEMMs) --------------------
#define T64_SZ  (64 * LDS_ * 2)
#define STAGE64 (2 * T64_SZ)
#define SMEMB64 (NSTG * STAGE64)

__device__ __forceinline__ void ld_tile_async64(
    const __half* __restrict__ g, int ldk, uint32_t sbase, int tid) {
#pragma unroll
    for (int i = 0; i < 2; ++i) {
        int idx = tid + i * 128;
        int row = idx >> 2, ch = idx & 3;
        CP_ASYNC16(sbase + row * (LDS_ * 2) + ch * 16,
                   g + (size_t)row * ldk + ch * 8);
    }
}

__global__ __launch_bounds__(128) void hmma_nt64_kernel(
    const __half* __restrict__ A, int lda, size_t sA,
    const __half* __restrict__ Bs, int ldb, size_t sB,
    __half* __restrict__ Ch, int ldc, size_t sC,
    const float* __restrict__ bias, int bias_mode, int sBias,
    int K) {
    extern __shared__ char smem[];
    const uint32_t sb = smem_u32(smem);
    const int tid = threadIdx.x;
    const int wid = tid >> 5, lane = tid & 31;
    const int wm = wid & 1, wn = wid >> 1;
    const int bz = blockIdx.z;
    const int m0 = blockIdx.y * 64, n0 = blockIdx.x * 64;

    const __half* gA = A  + (size_t)bz * sA + (size_t)m0 * lda;
    const __half* gB = Bs + (size_t)bz * sB + (size_t)n0 * ldb;

    float acc[2][4][4] = {};
    const int nt = K >> 5;
#pragma unroll
    for (int s = 0; s < NSTG - 1; ++s) {
        if (s < nt) {
            uint32_t st = sb + s * STAGE64;
            ld_tile_async64(gA + (s << 5), lda, st,          tid);
            ld_tile_async64(gB + (s << 5), ldb, st + T64_SZ, tid);
        }
        CP_COMMIT();
    }

    const int a_m  = wm * 32 + (lane & 15);
    const int a_k  = (lane >> 4) * 8;
    const int b_nr = wn * 32 + (lane & 7) + ((lane >> 4) << 3);
    const int b_k  = ((lane >> 3) & 1) * 8;

    for (int kt = 0; kt < nt; ++kt) {
        const int pre = kt + NSTG - 1;
        if (pre < nt) {
            uint32_t st = sb + (pre & (NSTG - 1)) * STAGE64;
            ld_tile_async64(gA + (pre << 5), lda, st,          tid);
            ld_tile_async64(gB + (pre << 5), ldb, st + T64_SZ, tid);
        }
        CP_COMMIT();
        const int rem = nt - 1 - kt;
        if (rem >= NSTG - 2) { CP_WAIT2(); }
        else if (rem == 1)   { CP_WAIT1(); }
        else                 { CP_WAIT0(); }
        __syncthreads();

        const uint32_t st = sb + (kt & (NSTG - 1)) * STAGE64;
#pragma unroll
        for (int ks = 0; ks < 2; ++ks) {
            const int kk = ks * 16;
            uint32_t ah[2][4], bb[2][4];
#pragma unroll
            for (int mi = 0; mi < 2; ++mi)
                ldsm_x4(ah[mi], st + (a_m + mi * 16) * (LDS_ * 2) + (kk + a_k) * 2);
#pragma unroll
            for (int nj = 0; nj < 2; ++nj)
                ldsm_x4(bb[nj], st + T64_SZ + (b_nr + nj * 16) * (LDS_ * 2) + (kk + b_k) * 2);
#pragma unroll
            for (int mi = 0; mi < 2; ++mi)
#pragma unroll
                for (int nj = 0; nj < 2; ++nj) {
                    mma16816(acc[mi][2 * nj],     ah[mi], bb[nj][0], bb[nj][1]);
                    mma16816(acc[mi][2 * nj + 1], ah[mi], bb[nj][2], bb[nj][3]);
                }
        }
        __syncthreads();
    }

    const int r_in = lane >> 2;
    const int c_in = (lane & 3) * 2;
    const float* bp = bias ? bias + bz * sBias : nullptr;
    __half* Hb = Ch + (size_t)bz * sC;
#pragma unroll
    for (int mi = 0; mi < 2; ++mi) {
        int row0 = m0 + wm * 32 + mi * 16 + r_in;
        int row1 = row0 + 8;
        float rb0 = 0.f, rb1 = 0.f;
        if (bias_mode == 1) { rb0 = bp[row0]; rb1 = bp[row1]; }
#pragma unroll
        for (int ni = 0; ni < 4; ++ni) {
            int col = n0 + wn * 32 + ni * 8 + c_in;
            float cb0 = 0.f, cb1 = 0.f;
            if (bias_mode == 2) { cb0 = bp[col]; cb1 = bp[col + 1]; }
            float v00 = acc[mi][ni][0] + rb0 + cb0;
            float v01 = acc[mi][ni][1] + rb0 + cb1;
            float v10 = acc[mi][ni][2] + rb1 + cb0;
            float v11 = acc[mi][ni][3] + rb1 + cb1;
            *(__half2*)(Hb + (size_t)row0 * ldc + col) =
                __halves2half2(__float2half_rn(v00), __float2half_rn(v01));
            *(__half2*)(Hb + (size_t)row1 * ldc + col) =
                __halves2half2(__float2half_rn(v10), __float2half_rn(v11));
        }
    }
}

// ---------------------------------------------------------------------------
// Launch sequence
// ---------------------------------------------------------------------------
extern "C" void kernel_launch(void* const* d_in, const int* in_sizes, int n_in,
                              void* d_out, int out_size) {
    const float* x        = (const float*)d_in[0];
    const float* qkv_w    = (const float*)d_in[1];
    const float* qkv_b    = (const float*)d_in[2];
    const float* proj_w   = (const float*)d_in[3];
    const float* proj_b   = (const float*)d_in[4];
    const float* gn_scale = (const float*)d_in[5];
    const float* gn_bias  = (const float*)d_in[6];
    float* out = (float*)d_out;

    cudaFuncSetAttribute(hmma_nt_kernel, cudaFuncAttributeMaxDynamicSharedMemorySize, SMEMB);
    cudaFuncSetAttribute(hmma_nt64_kernel, cudaFuncAttributeMaxDynamicSharedMemorySize, SMEMB64);

    float *biasb, *fb;
    __half *Wh, *xTh, *xh, *khl, *kh, *kxh, *ctxh, *Mh, *Eh, *wqTh, *pwh;
    cudaGetSymbolAddress((void**)&biasb, g_biasb);
    cudaGetSymbolAddress((void**)&fb, g_fb);
    cudaGetSymbolAddress((void**)&Wh, g_Wh);
    cudaGetSymbolAddress((void**)&xTh, g_xTh);
    cudaGetSymbolAddress((void**)&xh, g_xh);
    cudaGetSymbolAddress((void**)&khl, g_khl);
    cudaGetSymbolAddress((void**)&kh, g_kh);
    cudaGetSymbolAddress((void**)&kxh, g_kxh);
    cudaGetSymbolAddress((void**)&ctxh, g_ctxh);
    cudaGetSymbolAddress((void**)&Mh, g_Mh);
    cudaGetSymbolAddress((void**)&Eh, g_Eh);
    cudaGetSymbolAddress((void**)&wqTh, g_wqTh);
    cudaGetSymbolAddress((void**)&pwh, g_pwh);

    // 1) proj_w convert (+stats zero), fused x convert/transpose/stats,
    //    weight folding (stats finalized inline), q-slab transpose
    f2h_init_kernel<<<(C_ * C_ / 4 + 255) / 256, 256>>>(proj_w, pwh, C_ * C_ / 4);
    tconv_gn_kernel<<<dim3(N_ / 32, G_, B_), 256>>>(x, xTh, xh);
    prep_w_kernel<<<B_ * O3, 128>>>(qkv_w, qkv_b, gn_scale, gn_bias);
    wqt_kernel<<<dim3(C_ / 32, C_ / 32, B_), dim3(32, 8)>>>();
    // 2) k logits (fp16 out): k[d,n] = Wk . xT + bk
    hmma_nt_kernel<<<dim3(N_ / 128, C_ / 128, B_), 128, SMEMB>>>(
        Wh + (size_t)C_ * C_, C_, (size_t)O3 * C_,
        xTh, C_, (size_t)N_ * C_,
        nullptr, khl, N_, (size_t)C_ * N_,
        biasb + C_, 1, O3, nullptr, 0, C_);
    // 3) softmax over tokens
    softmax_kernel<<<B_ * C_, 256>>>(khl, kh);
    // 4) kx[d,c] = k_sm . x^T   (K=4096)
    hmma_nt64_kernel<<<dim3(C_ / 64, C_ / 64, B_), 128, SMEMB64>>>(
        kh, N_, (size_t)C_ * N_,
        xh, N_, (size_t)C_ * N_,
        kxh, C_, (size_t)C_ * C_,
        nullptr, 0, 0, N_);
    // 5) ctx[d,e] = kx . Wv^T + bv[e]
    hmma_nt64_kernel<<<dim3(C_ / 64, C_ / 64, B_), 128, SMEMB64>>>(
        kxh, C_, (size_t)C_ * C_,
        Wh + (size_t)2 * C_ * C_, C_, (size_t)O3 * C_,
        ctxh, C_, (size_t)C_ * C_,
        biasb + 2 * C_, 2, O3, C_);
    // 6) M[o,d] = proj_w . ctx^T
    hmma_nt64_kernel<<<dim3(C_ / 64, C_ / 64, B_), 128, SMEMB64>>>(
        pwh, C_, 0,
        ctxh, C_, (size_t)C_ * C_,
        Mh, C_, (size_t)C_ * C_,
        nullptr, 0, 0, C_);
    // 7) E[o,c] = M . WqT^T  (= M @ Wq)
    hmma_nt64_kernel<<<dim3(C_ / 64, C_ / 64, B_), 128, SMEMB64>>>(
        Mh, C_, (size_t)C_ * C_,
        wqTh, C_, (size_t)C_ * C_,
        Eh, C_, (size_t)C_ * C_,
        nullptr, 0, 0, C_);
    // 8) fb = proj_b + M @ bq
    fb_kernel<<<B_ * C_ / 8, 256>>>(proj_b);
    // 9) out[o,n] = E . xT^T + fb[o] + x
    hmma_nt_kernel<<<dim3(N_ / 128, C_ / 128, B_), 128, SMEMB>>>(
        Eh, C_, (size_t)C_ * C_,
        xTh, C_, (size_t)N_ * C_,
        out, nullptr, N_, (size_t)C_ * N_,
        fb, 1, C_, x, (size_t)C_ * N_, C_);
}

// round 11
// speedup vs baseline: 1.0809x; 1.0139x over previous
#include <cuda_runtime.h>
#include <cuda_fp16.h>
#include <cstdint>
#include <math.h>

// Problem constants
#define B_   8
#define C_   512
#define N_   4096
#define G_   8
#define CPG  64
#define O3   1536
#define EPSV 1e-6f
#define QSCALE 0.04419417382415922f   // 512^-0.5

// ---------------------------------------------------------------------------
// PTX helpers
// ---------------------------------------------------------------------------
__device__ __forceinline__ uint32_t smem_u32(const void* p) {
    uint32_t a;
    asm("{ .reg .u64 t; cvta.to.shared.u64 t, %1; cvt.u32.u64 %0, t; }" : "=r"(a) : "l"(p));
    return a;
}
__device__ __forceinline__ void ldsm_x4(uint32_t (&r)[4], uint32_t addr) {
    asm volatile("ldmatrix.sync.aligned.m8n8.x4.shared.b16 {%0,%1,%2,%3}, [%4];"
        : "=r"(r[0]), "=r"(r[1]), "=r"(r[2]), "=r"(r[3]) : "r"(addr));
}
__device__ __forceinline__ void mma16816(float (&d)[4], const uint32_t (&a)[4],
                                         uint32_t b0, uint32_t b1) {
    asm volatile(
        "mma.sync.aligned.m16n8k16.row.col.f32.f16.f16.f32 "
        "{%0,%1,%2,%3}, {%4,%5,%6,%7}, {%8,%9}, {%0,%1,%2,%3};"
        : "+f"(d[0]), "+f"(d[1]), "+f"(d[2]), "+f"(d[3])
        : "r"(a[0]), "r"(a[1]), "r"(a[2]), "r"(a[3]), "r"(b0), "r"(b1));
}
#define CP_ASYNC16(dst, src) \
    asm volatile("cp.async.cg.shared.global [%0], [%1], 16;" :: "r"(dst), "l"(src))
#define CP_COMMIT() asm volatile("cp.async.commit_group;" ::: "memory")
#define CP_WAIT0()  asm volatile("cp.async.wait_group 0;" ::: "memory")
#define CP_WAIT1()  asm volatile("cp.async.wait_group 1;" ::: "memory")
#define CP_WAIT2()  asm volatile("cp.async.wait_group 2;" ::: "memory")

// ---------------------------------------------------------------------------
// Scratch
// ---------------------------------------------------------------------------
__device__ __half g_Wh[(size_t)B_ * O3 * C_];
__device__ float  g_biasb[B_ * O3];
__device__ float  g_ssum[B_ * G_], g_ssq[B_ * G_];
__device__ __half g_xTh[(size_t)B_ * N_ * C_];        // x token-major fp16
__device__ __half g_xh [(size_t)B_ * C_ * N_];        // x channel-major fp16
__device__ __half g_khl[(size_t)B_ * C_ * N_];        // k logits fp16
__device__ __half g_kh[(size_t)B_ * C_ * N_];         // softmaxed k fp16
__device__ __half g_kxh[(size_t)B_ * C_ * C_];        // k_sm @ x^T
__device__ __half g_ctxh[(size_t)B_ * C_ * C_];
__device__ __half g_Mh[(size_t)B_ * C_ * C_];
__device__ __half g_Eh[(size_t)B_ * C_ * C_];         // M @ Wq
__device__ __half g_wqTh[(size_t)B_ * C_ * C_];       // Wq transposed [c,o]
__device__ __half g_pwh[C_ * C_];
__device__ float  g_fb[B_ * C_];                      // final fused bias

// ---------------------------------------------------------------------------
// Reductions
// ---------------------------------------------------------------------------
__device__ __forceinline__ float warp_sum(float v) {
#pragma unroll
    for (int o = 16; o > 0; o >>= 1) v += __shfl_xor_sync(0xffffffffu, v, o);
    return v;
}
__device__ __forceinline__ float warp_max(float v) {
#pragma unroll
    for (int o = 16; o > 0; o >>= 1) v = fmaxf(v, __shfl_xor_sync(0xffffffffu, v, o));
    return v;
}
__device__ __forceinline__ float block_sum(float v, float* sh) {
    int tid = threadIdx.x, nw = blockDim.x >> 5;
    __syncthreads();
    v = warp_sum(v);
    if ((tid & 31) == 0) sh[tid >> 5] = v;
    __syncthreads();
    if (tid < 32) {
        float w = (tid < nw) ? sh[tid] : 0.f;
        w = warp_sum(w);
        if (tid == 0) sh[0] = w;
    }
    __syncthreads();
    return sh[0];
}
__device__ __forceinline__ float block_max(float v, float* sh) {
    int tid = threadIdx.x, nw = blockDim.x >> 5;
    __syncthreads();
    v = warp_max(v);
    if ((tid & 31) == 0) sh[tid >> 5] = v;
    __syncthreads();
    if (tid < 32) {
        float w = (tid < nw) ? sh[tid] : -3.402823466e38f;
        w = warp_max(w);
        if (tid == 0) sh[0] = w;
    }
    __syncthreads();
    return sh[0];
}

// GN stats -> (mean, rstd) on the fly
__device__ __forceinline__ void gn_ms(int bg, float* mean, float* rstd) {
    const float inv = 1.f / (float)(CPG * N_);
    float m = g_ssum[bg] * inv;
    *mean = m;
    *rstd = rsqrtf(g_ssq[bg] * inv - m * m + EPSV);
}

// ---------------------------------------------------------------------------
// fp32 -> fp16 convert (proj_w) + GN stats zero-init (block 0)
// ---------------------------------------------------------------------------
__global__ __launch_bounds__(256) void f2h_init_kernel(
    const float* __restrict__ in, __half* __restrict__ out, size_t n4) {
    if (blockIdx.x == 0 && threadIdx.x < B_ * G_) {
        g_ssum[threadIdx.x] = 0.f;
        g_ssq[threadIdx.x] = 0.f;
    }
    size_t i = (size_t)blockIdx.x * 256 + threadIdx.x;
    if (i >= n4) return;
    float4 v = ((const float4*)in)[i];
    __half2* o = (__half2*)(out + i * 4);
    o[0] = __halves2half2(__float2half_rn(v.x), __float2half_rn(v.y));
    o[1] = __halves2half2(__float2half_rn(v.z), __float2half_rn(v.w));
}

// ---------------------------------------------------------------------------
// Fused: x [C,N] fp32 -> xh (fp16 same layout) + xT [N,C] fp16 + GN stats.
// grid (N/64, G, B), block 256. Tile: 64 channels (one group) x 64 tokens.
// ---------------------------------------------------------------------------
__global__ __launch_bounds__(256) void tconv_gn_kernel(
    const float* __restrict__ in, __half* __restrict__ outT,
    __half* __restrict__ outCh) {
    __shared__ float t[64][65];
    __shared__ float sh[32];
    int b = blockIdx.z, g = blockIdx.y;
    int n0 = blockIdx.x * 64, c0 = g * 64;
    const float* ip = in + (size_t)b * C_ * N_;
    __half* chp = outCh + (size_t)b * C_ * N_;
    int tid = threadIdx.x;
    int f4 = tid & 15, cr = tid >> 4;          // 16 col-quads x 16 rows/pass
    float s = 0.f, ss = 0.f;
#pragma unroll
    for (int p = 0; p < 4; ++p) {
        int c = cr + p * 16;
        float4 v = *(const float4*)(ip + (size_t)(c0 + c) * N_ + n0 + f4 * 4);
        s += v.x + v.y + v.z + v.w;
        ss = fmaf(v.x, v.x, fmaf(v.y, v.y, fmaf(v.z, v.z, fmaf(v.w, v.w, ss))));
        __half2 h01 = __halves2half2(__float2half_rn(v.x), __float2half_rn(v.y));
        __half2 h23 = __halves2half2(__float2half_rn(v.z), __float2half_rn(v.w));
        uint2 hw;
        hw.x = *(uint32_t*)&h01;
        hw.y = *(uint32_t*)&h23;
        *(uint2*)(chp + (size_t)(c0 + c) * N_ + n0 + f4 * 4) = hw;
        t[c][f4 * 4 + 0] = v.x; t[c][f4 * 4 + 1] = v.y;
        t[c][f4 * 4 + 2] = v.z; t[c][f4 * 4 + 3] = v.w;
    }
    float bs  = block_sum(s, sh);
    float bss = block_sum(ss, sh);
    if (tid == 0) {
        atomicAdd(&g_ssum[b * G_ + g], bs);
        atomicAdd(&g_ssq [b * G_ + g], bss);
    }
    // transpose out: each thread writes 8 consecutive c (16 B) per pass
    __half* op = outT + (size_t)b * N_ * C_;
    int c8 = (tid & 7) * 8, nr = tid >> 3;     // 8 c-octets x 32 n-rows/pass
#pragma unroll
    for (int p = 0; p < 2; ++p) {
        int n = nr + p * 32;
        __half2 h0 = __halves2half2(__float2half_rn(t[c8 + 0][n]),
                                    __float2half_rn(t[c8 + 1][n]));
        __half2 h1 = __halves2half2(__float2half_rn(t[c8 + 2][n]),
                                    __float2half_rn(t[c8 + 3][n]));
        __half2 h2 = __halves2half2(__float2half_rn(t[c8 + 4][n]),
                                    __float2half_rn(t[c8 + 5][n]));
        __half2 h3 = __halves2half2(__float2half_rn(t[c8 + 6][n]),
                                    __float2half_rn(t[c8 + 7][n]));
        uint4 w;
        w.x = *(uint32_t*)&h0; w.y = *(uint32_t*)&h1;
        w.z = *(uint32_t*)&h2; w.w = *(uint32_t*)&h3;
        *(uint4*)(op + (size_t)(n0 + n) * C_ + c0 + c8) = w;
    }
}

// ---------------------------------------------------------------------------
// Fold GN (+q scale) into qkv weights -> fp16; fold means into bias (fp32)
// grid B_*O3, block 128. Stats finalized inline.
// ---------------------------------------------------------------------------
__global__ __launch_bounds__(128) void prep_w_kernel(
    const float* __restrict__ qkv_w, const float* __restrict__ qkv_b,
    const float* __restrict__ gn_scale, const float* __restrict__ gn_bias) {
    int bo = blockIdx.x;
    int b = bo / O3, o = bo % O3;
    float qs = (o < C_) ? QSCALE : 1.f;
    const float* wrow = qkv_w + (size_t)o * C_;
    __half* wh = g_Wh + (size_t)bo * C_;
    float acc = 0.f;
#pragma unroll
    for (int i = 0; i < 4; ++i) {
        int c = threadIdx.x + i * 128;
        float mean, rstd;
        gn_ms(b * G_ + (c >> 6), &mean, &rstd);
        float a = rstd * gn_scale[c];
        float d = gn_bias[c] - mean * a;
        float w = wrow[c];
        wh[c] = __float2half_rn(w * a * qs);
        acc = fmaf(w, d, acc);
    }
    __shared__ float sh[32];
    acc = block_sum(acc, sh);
    if (threadIdx.x == 0) g_biasb[bo] = qs * (qkv_b[o] + acc);
}

// ---------------------------------------------------------------------------
// Transpose q-slab of folded weights: Wq [o,c] -> wqT [c,o]  (fp16)
// grid (C/64, C/64, B), block 256, uint2 global accesses.
// ---------------------------------------------------------------------------
__global__ __launch_bounds__(256) void wqt_kernel() {
    __shared__ __half t[64][70];
    int b = blockIdx.z;
    const __half* W = g_Wh + (size_t)b * O3 * C_;
    __half* outp = g_wqTh + (size_t)b * C_ * C_;
    int c0 = blockIdx.x * 64, o0 = blockIdx.y * 64;
    int tid = threadIdx.x;
    int q = tid & 15, r = tid >> 4;            // 16 quads x 16 rows/pass
#pragma unroll
    for (int p = 0; p < 4; ++p) {
        int o = r + p * 16;
        uint2 v = *(const uint2*)(W + (size_t)(o0 + o) * C_ + c0 + q * 4);
        __half2 h01 = *(__half2*)&v.x;
        __half2 h23 = *(__half2*)&v.y;
        t[o][q * 4 + 0] = __low2half(h01); t[o][q * 4 + 1] = __high2half(h01);
        t[o][q * 4 + 2] = __low2half(h23); t[o][q * 4 + 3] = __high2half(h23);
    }
    __syncthreads();
#pragma unroll
    for (int p = 0; p < 4; ++p) {
        int c = r + p * 16;
        __half2 a = __halves2half2(t[q * 4 + 0][c], t[q * 4 + 1][c]);
        __half2 d = __halves2half2(t[q * 4 + 2][c], t[q * 4 + 3][c]);
        uint2 w;
        w.x = *(uint32_t*)&a;
        w.y = *(uint32_t*)&d;
        *(uint2*)(outp + (size_t)(c0 + c) * C_ + o0 + q * 4) = w;
    }
}

// ---------------------------------------------------------------------------
// Row softmax: fp16 logits -> fp16 probabilities (fp32 math inside)
// ---------------------------------------------------------------------------
__global__ __launch_bounds__(256) void softmax_kernel(
    const __half* __restrict__ kl, __half* __restrict__ kh) {
    int row = blockIdx.x;
    const __half2* p = (const __half2*)(kl + (size_t)row * N_);
    __half2* o = (__half2*)(kh + (size_t)row * N_);
    const int tid = threadIdx.x;
    float2 v[8];
    float mx = -3.402823466e38f;
#pragma unroll
    for (int i = 0; i < 8; i++) {
        v[i] = __half22float2(p[tid + i * 256]);
        mx = fmaxf(mx, fmaxf(v[i].x, v[i].y));
    }
    __shared__ float sh[32];
    mx = block_max(mx, sh);
    float s = 0.f;
#pragma unroll
    for (int i = 0; i < 8; i++) {
        v[i].x = __expf(v[i].x - mx); v[i].y = __expf(v[i].y - mx);
        s += v[i].x + v[i].y;
    }
    s = block_sum(s, sh);
    float inv = 1.f / s;
#pragma unroll
    for (int i = 0; i < 8; i++) {
        o[tid + i * 256] = __halves2half2(__float2half_rn(v[i].x * inv),
                                          __float2half_rn(v[i].y * inv));
    }
}

// ---------------------------------------------------------------------------
// fb[b,o] = proj_b[o] + sum_d M[b,o,d] * bq_b[b,d]
// ---------------------------------------------------------------------------
__global__ __launch_bounds__(256) void fb_kernel(const float* __restrict__ proj_b) {
    int r = blockIdx.x * 8 + (threadIdx.x >> 5);
    int b = r / C_, o = r % C_;
    const __half* Mrow = g_Mh + ((size_t)b * C_ + o) * C_;
    const float* bq = g_biasb + b * O3;
    int lane = threadIdx.x & 31;
    float s = 0.f;
    for (int d = lane; d < C_; d += 32)
        s += __half2float(Mrow[d]) * bq[d];
    s = warp_sum(s);
    if (lane == 0) g_fb[r] = s + proj_b[o];
}

// ---------------------------------------------------------------------------
// Shared GEMM plumbing
// ---------------------------------------------------------------------------
#define LDS_   40
#define NSTG   4

// ---- 128x128 tile kernel -------------------------------------------------
#define T_SZ   (128 * LDS_ * 2)
#define STAGE  (2 * T_SZ)
#define SMEMB  (NSTG * STAGE)

__device__ __forceinline__ void ld_tile_async128(
    const __half* __restrict__ g, int ldk, uint32_t sbase, int tid) {
#pragma unroll
    for (int i = 0; i < 4; ++i) {
        int idx = tid + i * 128;
        int row = idx >> 2, ch = idx & 3;
        CP_ASYNC16(sbase + row * (LDS_ * 2) + ch * 16,
                   g + (size_t)row * ldk + ch * 8);
    }
}

__global__ __launch_bounds__(128) void hmma_nt_kernel(
    const __half* __restrict__ A, int lda, size_t sA,
    const __half* __restrict__ Bs, int ldb, size_t sB,
    float* __restrict__ Cf, __half* __restrict__ Ch, int ldc, size_t sC,
    const float* __restrict__ bias, int bias_mode, int sBias,
    const float* __restrict__ resid, size_t sR,
    int K) {
    extern __shared__ char smem[];
    const uint32_t sb = smem_u32(smem);
    const int tid = threadIdx.x;
    const int wid = tid >> 5, lane = tid & 31;
    const int wm = wid & 1, wn = wid >> 1;
    const int bz = blockIdx.z;
    const int m0 = blockIdx.y * 128, n0 = blockIdx.x * 128;

    const __half* gA = A  + (size_t)bz * sA + (size_t)m0 * lda;
    const __half* gB = Bs + (size_t)bz * sB + (size_t)n0 * ldb;

    float acc[4][8][4] = {};
    const int nt = K >> 5;
#pragma unroll
    for (int s = 0; s < NSTG - 1; ++s) {
        if (s < nt) {
            uint32_t st = sb + s * STAGE;
            ld_tile_async128(gA + (s << 5), lda, st,        tid);
            ld_tile_async128(gB + (s << 5), ldb, st + T_SZ, tid);
        }
        CP_COMMIT();
    }

    const int a_m  = wm * 64 + (lane & 15);
    const int a_k  = (lane >> 4) * 8;
    const int b_nr = wn * 64 + (lane & 7) + ((lane >> 4) << 3);
    const int b_k  = ((lane >> 3) & 1) * 8;

    for (int kt = 0; kt < nt; ++kt) {
        const int pre = kt + NSTG - 1;
        if (pre < nt) {
            uint32_t st = sb + (pre & (NSTG - 1)) * STAGE;
            ld_tile_async128(gA + (pre << 5), lda, st,        tid);
            ld_tile_async128(gB + (pre << 5), ldb, st + T_SZ, tid);
        }
        CP_COMMIT();
        const int rem = nt - 1 - kt;
        if (rem >= NSTG - 2) { CP_WAIT2(); }
        else if (rem == 1)   { CP_WAIT1(); }
        else                 { CP_WAIT0(); }
        __syncthreads();

        const uint32_t st = sb + (kt & (NSTG - 1)) * STAGE;
#pragma unroll
        for (int ks = 0; ks < 2; ++ks) {
            const int kk = ks * 16;
            uint32_t ah[4][4], bb[4][4];
#pragma unroll
            for (int mi = 0; mi < 4; ++mi)
                ldsm_x4(ah[mi], st + (a_m + mi * 16) * (LDS_ * 2) + (kk + a_k) * 2);
#pragma unroll
            for (int nj = 0; nj < 4; ++nj)
                ldsm_x4(bb[nj], st + T_SZ + (b_nr + nj * 16) * (LDS_ * 2) + (kk + b_k) * 2);
#pragma unroll
            for (int mi = 0; mi < 4; ++mi)
#pragma unroll
                for (int nj = 0; nj < 4; ++nj) {
                    mma16816(acc[mi][2 * nj],     ah[mi], bb[nj][0], bb[nj][1]);
                    mma16816(acc[mi][2 * nj + 1], ah[mi], bb[nj][2], bb[nj][3]);
                }
        }
        __syncthreads();
    }

    const int r_in = lane >> 2;
    const int c_in = (lane & 3) * 2;
    const float* bp = bias ? bias + bz * sBias : nullptr;
#pragma unroll
    for (int mi = 0; mi < 4; ++mi) {
        int row0 = m0 + wm * 64 + mi * 16 + r_in;
        int row1 = row0 + 8;
        float rb0 = 0.f, rb1 = 0.f;
        if (bias_mode == 1) { rb0 = bp[row0]; rb1 = bp[row1]; }
#pragma unroll
        for (int ni = 0; ni < 8; ++ni) {
            int col = n0 + wn * 64 + ni * 8 + c_in;
            float cb0 = 0.f, cb1 = 0.f;
            if (bias_mode == 2) { cb0 = bp[col]; cb1 = bp[col + 1]; }
            float v00 = acc[mi][ni][0] + rb0 + cb0;
            float v01 = acc[mi][ni][1] + rb0 + cb1;
            float v10 = acc[mi][ni][2] + rb1 + cb0;
            float v11 = acc[mi][ni][3] + rb1 + cb1;
            if (Cf) {
                float* Cb = Cf + (size_t)bz * sC;
                if (resid) {
                    const float* Rb = resid + (size_t)bz * sR;
                    float2 r0 = *(const float2*)(Rb + (size_t)row0 * ldc + col);
                    float2 r1 = *(const float2*)(Rb + (size_t)row1 * ldc + col);
                    v00 += r0.x; v01 += r0.y; v10 += r1.x; v11 += r1.y;
                }
                *(float2*)(Cb + (size_t)row0 * ldc + col) = make_float2(v00, v01);
                *(float2*)(Cb + (size_t)row1 * ldc + col) = make_float2(v10, v11);
            } else {
                __half* Hb = Ch + (size_t)bz * sC;
                *(__half2*)(Hb + (size_t)row0 * ldc + col) =
                    __halves2half2(__float2half_rn(v00), __float2half_rn(v01));
                *(__half2*)(Hb + (size_t)row1 * ldc + col) =
                    __halves2half2(__float2half_rn(v10), __float2half_rn(v11));
            }
        }
    }
}

// ---- 64x64 tile kernel (fp32 accum; for M=N=512 GEMMs) --------------------
#define T64_SZ  (64 * LDS_ * 2)
#define STAGE64 (2 * T64_SZ)
#define SMEMB64 (NSTG * STAGE64)

__device__ __forceinline__ void ld_tile_async64(
    const __half* __restrict__ g, int ldk, uint32_t sbase, int tid) {
#pragma unroll
    for (int i = 0; i < 2; ++i) {
        int idx = tid + i * 128;
        int row = idx >> 2, ch = idx & 3;
        CP_ASYNC16(sbase + row * (LDS_ * 2) + ch * 16,
                   g + (size_t)row * ldk + ch * 8);
    }
}

__global__ __launch_bounds__(128) void hmma_nt64_kernel(
    const __half* __restrict__ A, int lda, size_t sA,
    const __half* __restrict__ Bs, int ldb, size_t sB,
    __half* __restrict__ Ch, int ldc, size_t sC,
    const float* __restrict__ bias, int bias_mode, int sBias,
    int K) {
    extern __shared__ char smem[];
    const uint32_t sb = smem_u32(smem);
    const int tid = threadIdx.x;
    const int wid = tid >> 5, lane = tid & 31;
    const int wm = wid & 1, wn = wid >> 1;
    const int bz = blockIdx.z;
    const int m0 = blockIdx.y * 64, n0 = blockIdx.x * 64;

    const __half* gA = A  + (size_t)bz * sA + (size_t)m0 * lda;
    const __half* gB = Bs + (size_t)bz * sB + (size_t)n0 * ldb;

    float acc[2][4][4] = {};
    const int nt = K >> 5;
#pragma unroll
    for (int s = 0; s < NSTG - 1; ++s) {
        if (s < nt) {
            uint32_t st = sb + s * STAGE64;
            ld_tile_async64(gA + (s << 5), lda, st,          tid);
            ld_tile_async64(gB + (s << 5), ldb, st + T64_SZ, tid);
        }
        CP_COMMIT();
    }

    const int a_m  = wm * 32 + (lane & 15);
    const int a_k  = (lane >> 4) * 8;
    const int b_nr = wn * 32 + (lane & 7) + ((lane >> 4) << 3);
    const int b_k  = ((lane >> 3) & 1) * 8;

    for (int kt = 0; kt < nt; ++kt) {
        const int pre = kt + NSTG - 1;
        if (pre < nt) {
            uint32_t st = sb + (pre & (NSTG - 1)) * STAGE64;
            ld_tile_async64(gA + (pre << 5), lda, st,          tid);
            ld_tile_async64(gB + (pre << 5), ldb, st + T64_SZ, tid);
        }
        CP_COMMIT();
        const int rem = nt - 1 - kt;
        if (rem >= NSTG - 2) { CP_WAIT2(); }
        else if (rem == 1)   { CP_WAIT1(); }
        else                 { CP_WAIT0(); }
        __syncthreads();

        const uint32_t st = sb + (kt & (NSTG - 1)) * STAGE64;
#pragma unroll
        for (int ks = 0; ks < 2; ++ks) {
            const int kk = ks * 16;
            uint32_t ah[2][4], bb[2][4];
#pragma unroll
            for (int mi = 0; mi < 2; ++mi)
                ldsm_x4(ah[mi], st + (a_m + mi * 16) * (LDS_ * 2) + (kk + a_k) * 2);
#pragma unroll
            for (int nj = 0; nj < 2; ++nj)
                ldsm_x4(bb[nj], st + T64_SZ + (b_nr + nj * 16) * (LDS_ * 2) + (kk + b_k) * 2);
#pragma unroll
            for (int mi = 0; mi < 2; ++mi)
#pragma unroll
                for (int nj = 0; nj < 2; ++nj) {
                    mma16816(acc[mi][2 * nj],     ah[mi], bb[nj][0], bb[nj][1]);
                    mma16816(acc[mi][2 * nj + 1], ah[mi], bb[nj][2], bb[nj][3]);
                }
        }
        __syncthreads();
    }

    const int r_in = lane >> 2;
    const int c_in = (lane & 3) * 2;
    const float* bp = bias ? bias + bz * sBias : nullptr;
    __half* Hb = Ch + (size_t)bz * sC;
#pragma unroll
    for (int mi = 0; mi < 2; ++mi) {
        int row0 = m0 + wm * 32 + mi * 16 + r_in;
        int row1 = row0 + 8;
        float rb0 = 0.f, rb1 = 0.f;
        if (bias_mode == 1) { rb0 = bp[row0]; rb1 = bp[row1]; }
#pragma unroll
        for (int ni = 0; ni < 4; ++ni) {
            int col = n0 + wn * 32 + ni * 8 + c_in;
            float cb0 = 0.f, cb1 = 0.f;
            if (bias_mode == 2) { cb0 = bp[col]; cb1 = bp[col + 1]; }
            float v00 = acc[mi][ni][0] + rb0 + cb0;
            float v01 = acc[mi][ni][1] + rb0 + cb1;
            float v10 = acc[mi][ni][2] + rb1 + cb0;
            float v11 = acc[mi][ni][3] + rb1 + cb1;
            *(__half2*)(Hb + (size_t)row0 * ldc + col) =
                __halves2half2(__float2half_rn(v00), __float2half_rn(v01));
            *(__half2*)(Hb + (size_t)row1 * ldc + col) =
                __halves2half2(__float2half_rn(v10), __float2half_rn(v11));
        }
    }
}

// ---------------------------------------------------------------------------
// Launch sequence
// ---------------------------------------------------------------------------
extern "C" void kernel_launch(void* const* d_in, const int* in_sizes, int n_in,
                              void* d_out, int out_size) {
    const float* x        = (const float*)d_in[0];
    const float* qkv_w    = (const float*)d_in[1];
    const float* qkv_b    = (const float*)d_in[2];
    const float* proj_w   = (const float*)d_in[3];
    const float* proj_b   = (const float*)d_in[4];
    const float* gn_scale = (const float*)d_in[5];
    const float* gn_bias  = (const float*)d_in[6];
    float* out = (float*)d_out;

    cudaFuncSetAttribute(hmma_nt_kernel, cudaFuncAttributeMaxDynamicSharedMemorySize, SMEMB);
    cudaFuncSetAttribute(hmma_nt64_kernel, cudaFuncAttributeMaxDynamicSharedMemorySize, SMEMB64);

    float *biasb, *fb;
    __half *Wh, *xTh, *xh, *khl, *kh, *kxh, *ctxh, *Mh, *Eh, *wqTh, *pwh;
    cudaGetSymbolAddress((void**)&biasb, g_biasb);
    cudaGetSymbolAddress((void**)&fb, g_fb);
    cudaGetSymbolAddress((void**)&Wh, g_Wh);
    cudaGetSymbolAddress((void**)&xTh, g_xTh);
    cudaGetSymbolAddress((void**)&xh, g_xh);
    cudaGetSymbolAddress((void**)&khl, g_khl);
    cudaGetSymbolAddress((void**)&kh, g_kh);
    cudaGetSymbolAddress((void**)&kxh, g_kxh);
    cudaGetSymbolAddress((void**)&ctxh, g_ctxh);
    cudaGetSymbolAddress((void**)&Mh, g_Mh);
    cudaGetSymbolAddress((void**)&Eh, g_Eh);
    cudaGetSymbolAddress((void**)&wqTh, g_wqTh);
    cudaGetSymbolAddress((void**)&pwh, g_pwh);

    // 1) proj_w convert (+stats zero), fused x convert/transpose/stats,
    //    weight folding (stats finalized inline), q-slab transpose
    f2h_init_kernel<<<(C_ * C_ / 4 + 255) / 256, 256>>>(proj_w, pwh, C_ * C_ / 4);
    tconv_gn_kernel<<<dim3(N_ / 64, G_, B_), 256>>>(x, xTh, xh);
    prep_w_kernel<<<B_ * O3, 128>>>(qkv_w, qkv_b, gn_scale, gn_bias);
    wqt_kernel<<<dim3(C_ / 64, C_ / 64, B_), 256>>>();
    // 2) k logits (fp16 out): k[d,n] = Wk . xT + bk
    hmma_nt_kernel<<<dim3(N_ / 128, C_ / 128, B_), 128, SMEMB>>>(
        Wh + (size_t)C_ * C_, C_, (size_t)O3 * C_,
        xTh, C_, (size_t)N_ * C_,
        nullptr, khl, N_, (size_t)C_ * N_,
        biasb + C_, 1, O3, nullptr, 0, C_);
    // 3) softmax over tokens
    softmax_kernel<<<B_ * C_, 256>>>(khl, kh);
    // 4) kx[d,c] = k_sm . x^T   (K=4096)
    hmma_nt64_kernel<<<dim3(C_ / 64, C_ / 64, B_), 128, SMEMB64>>>(
        kh, N_, (size_t)C_ * N_,
        xh, N_, (size_t)C_ * N_,
        kxh, C_, (size_t)C_ * C_,
        nullptr, 0, 0, N_);
    // 5) ctx[d,e] = kx . Wv^T + bv[e]
    hmma_nt64_kernel<<<dim3(C_ / 64, C_ / 64, B_), 128, SMEMB64>>>(
        kxh, C_, (size_t)C_ * C_,
        Wh + (size_t)2 * C_ * C_, C_, (size_t)O3 * C_,
        ctxh, C_, (size_t)C_ * C_,
        biasb + 2 * C_, 2, O3, C_);
    // 6) M[o,d] = proj_w . ctx^T
    hmma_nt64_kernel<<<dim3(C_ / 64, C_ / 64, B_), 128, SMEMB64>>>(
        pwh, C_, 0,
        ctxh, C_, (size_t)C_ * C_,
        Mh, C_, (size_t)C_ * C_,
        nullptr, 0, 0, C_);
    // 7) E[o,c] = M . WqT^T  (= M @ Wq)
    hmma_nt64_kernel<<<dim3(C_ / 64, C_ / 64, B_), 128, SMEMB64>>>(
        Mh, C_, (size_t)C_ * C_,
        wqTh, C_, (size_t)C_ * C_,
        Eh, C_, (size_t)C_ * C_,
        nullptr, 0, 0, C_);
    // 8) fb = proj_b + M @ bq
    fb_kernel<<<B_ * C_ / 8, 256>>>(proj_b);
    // 9) out[o,n] = E . xT^T + fb[o] + x
    hmma_nt_kernel<<<dim3(N_ / 128, C_ / 128, B_), 128, SMEMB>>>(
        Eh, C_, (size_t)C_ * C_,
        xTh, C_, (size_t)N_ * C_,
        out, nullptr, N_, (size_t)C_ * N_,
        fb, 1, C_, x, (size_t)C_ * N_, C_);
}

// round 12
// speedup vs baseline: 1.1099x; 1.0269x over previous
#include <cuda_runtime.h>
#include <cuda_fp16.h>
#include <cstdint>
#include <math.h>

// Problem constants
#define B_   8
#define C_   512
#define N_   4096
#define G_   8
#define CPG  64
#define O3   1536
#define EPSV 1e-6f
#define QSCALE 0.04419417382415922f   // 512^-0.5

// ---------------------------------------------------------------------------
// PTX helpers
// ---------------------------------------------------------------------------
__device__ __forceinline__ uint32_t smem_u32(const void* p) {
    uint32_t a;
    asm("{ .reg .u64 t; cvta.to.shared.u64 t, %1; cvt.u32.u64 %0, t; }" : "=r"(a) : "l"(p));
    return a;
}
__device__ __forceinline__ void ldsm_x4(uint32_t (&r)[4], uint32_t addr) {
    asm volatile("ldmatrix.sync.aligned.m8n8.x4.shared.b16 {%0,%1,%2,%3}, [%4];"
        : "=r"(r[0]), "=r"(r[1]), "=r"(r[2]), "=r"(r[3]) : "r"(addr));
}
__device__ __forceinline__ void mma16816(float (&d)[4], const uint32_t (&a)[4],
                                         uint32_t b0, uint32_t b1) {
    asm volatile(
        "mma.sync.aligned.m16n8k16.row.col.f32.f16.f16.f32 "
        "{%0,%1,%2,%3}, {%4,%5,%6,%7}, {%8,%9}, {%0,%1,%2,%3};"
        : "+f"(d[0]), "+f"(d[1]), "+f"(d[2]), "+f"(d[3])
        : "r"(a[0]), "r"(a[1]), "r"(a[2]), "r"(a[3]), "r"(b0), "r"(b1));
}
#define CP_ASYNC16(dst, src) \
    asm volatile("cp.async.cg.shared.global [%0], [%1], 16;" :: "r"(dst), "l"(src))
#define CP_COMMIT() asm volatile("cp.async.commit_group;" ::: "memory")
#define CP_WAIT0()  asm volatile("cp.async.wait_group 0;" ::: "memory")
#define CP_WAIT1()  asm volatile("cp.async.wait_group 1;" ::: "memory")
#define CP_WAIT2()  asm volatile("cp.async.wait_group 2;" ::: "memory")

#define NSM_SLOTS 296     // 2 blocks/SM x 148 SMs (persistent grid for big GEMM)

// ---------------------------------------------------------------------------
// Scratch
// ---------------------------------------------------------------------------
__device__ __half g_Wh[(size_t)B_ * O3 * C_];
__device__ float  g_biasb[B_ * O3];
__device__ float  g_ssum[B_ * G_], g_ssq[B_ * G_];
__device__ __half g_xTh[(size_t)B_ * N_ * C_];        // x token-major fp16
__device__ __half g_xh [(size_t)B_ * C_ * N_];        // x channel-major fp16
__device__ __half g_khl[(size_t)B_ * C_ * N_];        // k logits fp16
__device__ __half g_kh[(size_t)B_ * C_ * N_];         // softmaxed k fp16
__device__ __half g_kxh[(size_t)B_ * C_ * C_];        // k_sm @ x^T
__device__ __half g_ctxh[(size_t)B_ * C_ * C_];
__device__ __half g_Mh[(size_t)B_ * C_ * C_];
__device__ __half g_Eh[(size_t)B_ * C_ * C_];         // M @ Wq
__device__ __half g_wqTh[(size_t)B_ * C_ * C_];       // Wq transposed [c,o]
__device__ __half g_pwh[C_ * C_];
__device__ float  g_fb[B_ * C_];                      // final fused bias

// ---------------------------------------------------------------------------
// Reductions
// ---------------------------------------------------------------------------
__device__ __forceinline__ float warp_sum(float v) {
#pragma unroll
    for (int o = 16; o > 0; o >>= 1) v += __shfl_xor_sync(0xffffffffu, v, o);
    return v;
}
__device__ __forceinline__ float warp_max(float v) {
#pragma unroll
    for (int o = 16; o > 0; o >>= 1) v = fmaxf(v, __shfl_xor_sync(0xffffffffu, v, o));
    return v;
}
__device__ __forceinline__ float block_sum(float v, float* sh) {
    int tid = threadIdx.x, nw = blockDim.x >> 5;
    __syncthreads();
    v = warp_sum(v);
    if ((tid & 31) == 0) sh[tid >> 5] = v;
    __syncthreads();
    if (tid < 32) {
        float w = (tid < nw) ? sh[tid] : 0.f;
        w = warp_sum(w);
        if (tid == 0) sh[0] = w;
    }
    __syncthreads();
    return sh[0];
}
__device__ __forceinline__ float block_max(float v, float* sh) {
    int tid = threadIdx.x, nw = blockDim.x >> 5;
    __syncthreads();
    v = warp_max(v);
    if ((tid & 31) == 0) sh[tid >> 5] = v;
    __syncthreads();
    if (tid < 32) {
        float w = (tid < nw) ? sh[tid] : -3.402823466e38f;
        w = warp_max(w);
        if (tid == 0) sh[0] = w;
    }
    __syncthreads();
    return sh[0];
}

// GN stats -> (mean, rstd) on the fly
__device__ __forceinline__ void gn_ms(int bg, float* mean, float* rstd) {
    const float inv = 1.f / (float)(CPG * N_);
    float m = g_ssum[bg] * inv;
    *mean = m;
    *rstd = rsqrtf(g_ssq[bg] * inv - m * m + EPSV);
}

// ---------------------------------------------------------------------------
// fp32 -> fp16 convert (proj_w) + GN stats zero-init (block 0)
// ---------------------------------------------------------------------------
__global__ __launch_bounds__(256) void f2h_init_kernel(
    const float* __restrict__ in, __half* __restrict__ out, size_t n4) {
    if (blockIdx.x == 0 && threadIdx.x < B_ * G_) {
        g_ssum[threadIdx.x] = 0.f;
        g_ssq[threadIdx.x] = 0.f;
    }
    size_t i = (size_t)blockIdx.x * 256 + threadIdx.x;
    if (i >= n4) return;
    float4 v = ((const float4*)in)[i];
    __half2* o = (__half2*)(out + i * 4);
    o[0] = __halves2half2(__float2half_rn(v.x), __float2half_rn(v.y));
    o[1] = __halves2half2(__float2half_rn(v.z), __float2half_rn(v.w));
}

// ---------------------------------------------------------------------------
// Fused: x [C,N] fp32 -> xh (fp16 same layout) + xT [N,C] fp16 + GN stats.
// grid (N/64, G, B), block 256.
// ---------------------------------------------------------------------------
__global__ __launch_bounds__(256) void tconv_gn_kernel(
    const float* __restrict__ in, __half* __restrict__ outT,
    __half* __restrict__ outCh) {
    __shared__ float t[64][65];
    __shared__ float sh[32];
    int b = blockIdx.z, g = blockIdx.y;
    int n0 = blockIdx.x * 64, c0 = g * 64;
    const float* ip = in + (size_t)b * C_ * N_;
    __half* chp = outCh + (size_t)b * C_ * N_;
    int tid = threadIdx.x;
    int f4 = tid & 15, cr = tid >> 4;
    float s = 0.f, ss = 0.f;
#pragma unroll
    for (int p = 0; p < 4; ++p) {
        int c = cr + p * 16;
        float4 v = *(const float4*)(ip + (size_t)(c0 + c) * N_ + n0 + f4 * 4);
        s += v.x + v.y + v.z + v.w;
        ss = fmaf(v.x, v.x, fmaf(v.y, v.y, fmaf(v.z, v.z, fmaf(v.w, v.w, ss))));
        __half2 h01 = __halves2half2(__float2half_rn(v.x), __float2half_rn(v.y));
        __half2 h23 = __halves2half2(__float2half_rn(v.z), __float2half_rn(v.w));
        uint2 hw;
        hw.x = *(uint32_t*)&h01;
        hw.y = *(uint32_t*)&h23;
        *(uint2*)(chp + (size_t)(c0 + c) * N_ + n0 + f4 * 4) = hw;
        t[c][f4 * 4 + 0] = v.x; t[c][f4 * 4 + 1] = v.y;
        t[c][f4 * 4 + 2] = v.z; t[c][f4 * 4 + 3] = v.w;
    }
    float bs  = block_sum(s, sh);
    float bss = block_sum(ss, sh);
    if (tid == 0) {
        atomicAdd(&g_ssum[b * G_ + g], bs);
        atomicAdd(&g_ssq [b * G_ + g], bss);
    }
    __half* op = outT + (size_t)b * N_ * C_;
    int c8 = (tid & 7) * 8, nr = tid >> 3;
#pragma unroll
    for (int p = 0; p < 2; ++p) {
        int n = nr + p * 32;
        __half2 h0 = __halves2half2(__float2half_rn(t[c8 + 0][n]),
                                    __float2half_rn(t[c8 + 1][n]));
        __half2 h1 = __halves2half2(__float2half_rn(t[c8 + 2][n]),
                                    __float2half_rn(t[c8 + 3][n]));
        __half2 h2 = __halves2half2(__float2half_rn(t[c8 + 4][n]),
                                    __float2half_rn(t[c8 + 5][n]));
        __half2 h3 = __halves2half2(__float2half_rn(t[c8 + 6][n]),
                                    __float2half_rn(t[c8 + 7][n]));
        uint4 w;
        w.x = *(uint32_t*)&h0; w.y = *(uint32_t*)&h1;
        w.z = *(uint32_t*)&h2; w.w = *(uint32_t*)&h3;
        *(uint4*)(op + (size_t)(n0 + n) * C_ + c0 + c8) = w;
    }
}

// ---------------------------------------------------------------------------
// Fold GN (+q scale) into qkv weights -> fp16; fold means into bias (fp32)
// ---------------------------------------------------------------------------
__global__ __launch_bounds__(128) void prep_w_kernel(
    const float* __restrict__ qkv_w, const float* __restrict__ qkv_b,
    const float* __restrict__ gn_scale, const float* __restrict__ gn_bias) {
    int bo = blockIdx.x;
    int b = bo / O3, o = bo % O3;
    float qs = (o < C_) ? QSCALE : 1.f;
    const float* wrow = qkv_w + (size_t)o * C_;
    __half* wh = g_Wh + (size_t)bo * C_;
    float acc = 0.f;
#pragma unroll
    for (int i = 0; i < 4; ++i) {
        int c = threadIdx.x + i * 128;
        float mean, rstd;
        gn_ms(b * G_ + (c >> 6), &mean, &rstd);
        float a = rstd * gn_scale[c];
        float d = gn_bias[c] - mean * a;
        float w = wrow[c];
        wh[c] = __float2half_rn(w * a * qs);
        acc = fmaf(w, d, acc);
    }
    __shared__ float sh[32];
    acc = block_sum(acc, sh);
    if (threadIdx.x == 0) g_biasb[bo] = qs * (qkv_b[o] + acc);
}

// ---------------------------------------------------------------------------
// Transpose q-slab of folded weights: Wq [o,c] -> wqT [c,o]  (fp16)
// ---------------------------------------------------------------------------
__global__ __launch_bounds__(256) void wqt_kernel() {
    __shared__ __half t[64][70];
    int b = blockIdx.z;
    const __half* W = g_Wh + (size_t)b * O3 * C_;
    __half* outp = g_wqTh + (size_t)b * C_ * C_;
    int c0 = blockIdx.x * 64, o0 = blockIdx.y * 64;
    int tid = threadIdx.x;
    int q = tid & 15, r = tid >> 4;
#pragma unroll
    for (int p = 0; p < 4; ++p) {
        int o = r + p * 16;
        uint2 v = *(const uint2*)(W + (size_t)(o0 + o) * C_ + c0 + q * 4);
        __half2 h01 = *(__half2*)&v.x;
        __half2 h23 = *(__half2*)&v.y;
        t[o][q * 4 + 0] = __low2half(h01); t[o][q * 4 + 1] = __high2half(h01);
        t[o][q * 4 + 2] = __low2half(h23); t[o][q * 4 + 3] = __high2half(h23);
    }
    __syncthreads();
#pragma unroll
    for (int p = 0; p < 4; ++p) {
        int c = r + p * 16;
        __half2 a = __halves2half2(t[q * 4 + 0][c], t[q * 4 + 1][c]);
        __half2 d = __halves2half2(t[q * 4 + 2][c], t[q * 4 + 3][c]);
        uint2 w;
        w.x = *(uint32_t*)&a;
        w.y = *(uint32_t*)&d;
        *(uint2*)(outp + (size_t)(c0 + c) * C_ + o0 + q * 4) = w;
    }
}

// ---------------------------------------------------------------------------
// Row softmax: fp16 logits -> fp16 probabilities (fp32 math inside)
// ---------------------------------------------------------------------------
__global__ __launch_bounds__(256) void softmax_kernel(
    const __half* __restrict__ kl, __half* __restrict__ kh) {
    int row = blockIdx.x;
    const __half2* p = (const __half2*)(kl + (size_t)row * N_);
    __half2* o = (__half2*)(kh + (size_t)row * N_);
    const int tid = threadIdx.x;
    float2 v[8];
    float mx = -3.402823466e38f;
#pragma unroll
    for (int i = 0; i < 8; i++) {
        v[i] = __half22float2(p[tid + i * 256]);
        mx = fmaxf(mx, fmaxf(v[i].x, v[i].y));
    }
    __shared__ float sh[32];
    mx = block_max(mx, sh);
    float s = 0.f;
#pragma unroll
    for (int i = 0; i < 8; i++) {
        v[i].x = __expf(v[i].x - mx); v[i].y = __expf(v[i].y - mx);
        s += v[i].x + v[i].y;
    }
    s = block_sum(s, sh);
    float inv = 1.f / s;
#pragma unroll
    for (int i = 0; i < 8; i++) {
        o[tid + i * 256] = __halves2half2(__float2half_rn(v[i].x * inv),
                                          __float2half_rn(v[i].y * inv));
    }
}

// ---------------------------------------------------------------------------
// fb[b,o] = proj_b[o] + sum_d M[b,o,d] * bq_b[b,d]
// ---------------------------------------------------------------------------
__global__ __launch_bounds__(256) void fb_kernel(const float* __restrict__ proj_b) {
    int r = blockIdx.x * 8 + (threadIdx.x >> 5);
    int b = r / C_, o = r % C_;
    const __half* Mrow = g_Mh + ((size_t)b * C_ + o) * C_;
    const float* bq = g_biasb + b * O3;
    int lane = threadIdx.x & 31;
    float s = 0.f;
    for (int d = lane; d < C_; d += 32)
        s += __half2float(Mrow[d]) * bq[d];
    s = warp_sum(s);
    if (lane == 0) g_fb[r] = s + proj_b[o];
}

// ---------------------------------------------------------------------------
// Shared GEMM plumbing
// ---------------------------------------------------------------------------
#define LDS_   40
#define NSTG   4

// ---- 128x128 tile PERSISTENT kernel --------------------------------------
#define T_SZ   (128 * LDS_ * 2)
#define STAGE  (2 * T_SZ)
#define SMEMB  (NSTG * STAGE)

__device__ __forceinline__ void ld_tile_async128(
    const __half* __restrict__ g, int ldk, uint32_t sbase, int tid) {
#pragma unroll
    for (int i = 0; i < 4; ++i) {
        int idx = tid + i * 128;
        int row = idx >> 2, ch = idx & 3;
        CP_ASYNC16(sbase + row * (LDS_ * 2) + ch * 16,
                   g + (size_t)row * ldk + ch * 8);
    }
}

__global__ __launch_bounds__(128) void hmma_nt_kernel(
    const __half* __restrict__ A, int lda, size_t sA,
    const __half* __restrict__ Bs, int ldb, size_t sB,
    float* __restrict__ Cf, __half* __restrict__ Ch, int ldc, size_t sC,
    const float* __restrict__ bias, int bias_mode, int sBias,
    const float* __restrict__ resid, size_t sR,
    int K, int ntx, int nty) {
    extern __shared__ char smem[];
    const uint32_t sb = smem_u32(smem);
    const int tid = threadIdx.x;
    const int wid = tid >> 5, lane = tid & 31;
    const int wm = wid & 1, wn = wid >> 1;
    const int nt = K >> 5;

    const int a_m  = wm * 64 + (lane & 15);
    const int a_k  = (lane >> 4) * 8;
    const int b_nr = wn * 64 + (lane & 7) + ((lane >> 4) << 3);
    const int b_k  = ((lane >> 3) & 1) * 8;
    const int r_in = lane >> 2;
    const int c_in = (lane & 3) * 2;

    const int tiles_per_b = ntx * nty;
    const int tot = tiles_per_b * B_;

    for (int t = blockIdx.x; t < tot; t += gridDim.x) {
        const int bz = t / tiles_per_b;
        const int rem = t - bz * tiles_per_b;
        const int by = rem / ntx;
        const int bx = rem - by * ntx;
        const int m0 = by * 128, n0 = bx * 128;

        const __half* gA = A  + (size_t)bz * sA + (size_t)m0 * lda;
        const __half* gB = Bs + (size_t)bz * sB + (size_t)n0 * ldb;

        float acc[4][8][4] = {};
#pragma unroll
        for (int s = 0; s < NSTG - 1; ++s) {
            if (s < nt) {
                uint32_t st = sb + s * STAGE;
                ld_tile_async128(gA + (s << 5), lda, st,        tid);
                ld_tile_async128(gB + (s << 5), ldb, st + T_SZ, tid);
            }
            CP_COMMIT();
        }

        for (int kt = 0; kt < nt; ++kt) {
            const int pre = kt + NSTG - 1;
            if (pre < nt) {
                uint32_t st = sb + (pre & (NSTG - 1)) * STAGE;
                ld_tile_async128(gA + (pre << 5), lda, st,        tid);
                ld_tile_async128(gB + (pre << 5), ldb, st + T_SZ, tid);
            }
            CP_COMMIT();
            const int rm = nt - 1 - kt;
            if (rm >= NSTG - 2) { CP_WAIT2(); }
            else if (rm == 1)   { CP_WAIT1(); }
            else                { CP_WAIT0(); }
            __syncthreads();

            const uint32_t st = sb + (kt & (NSTG - 1)) * STAGE;
#pragma unroll
            for (int ks = 0; ks < 2; ++ks) {
                const int kk = ks * 16;
                uint32_t ah[4][4], bb[4][4];
#pragma unroll
                for (int mi = 0; mi < 4; ++mi)
                    ldsm_x4(ah[mi], st + (a_m + mi * 16) * (LDS_ * 2) + (kk + a_k) * 2);
#pragma unroll
                for (int nj = 0; nj < 4; ++nj)
                    ldsm_x4(bb[nj], st + T_SZ + (b_nr + nj * 16) * (LDS_ * 2) + (kk + b_k) * 2);
#pragma unroll
                for (int mi = 0; mi < 4; ++mi)
#pragma unroll
                    for (int nj = 0; nj < 4; ++nj) {
                        mma16816(acc[mi][2 * nj],     ah[mi], bb[nj][0], bb[nj][1]);
                        mma16816(acc[mi][2 * nj + 1], ah[mi], bb[nj][2], bb[nj][3]);
                    }
            }
            __syncthreads();
        }

        const float* bp = bias ? bias + bz * sBias : nullptr;
#pragma unroll
        for (int mi = 0; mi < 4; ++mi) {
            int row0 = m0 + wm * 64 + mi * 16 + r_in;
            int row1 = row0 + 8;
            float rb0 = 0.f, rb1 = 0.f;
            if (bias_mode == 1) { rb0 = bp[row0]; rb1 = bp[row1]; }
#pragma unroll
            for (int ni = 0; ni < 8; ++ni) {
                int col = n0 + wn * 64 + ni * 8 + c_in;
                float cb0 = 0.f, cb1 = 0.f;
                if (bias_mode == 2) { cb0 = bp[col]; cb1 = bp[col + 1]; }
                float v00 = acc[mi][ni][0] + rb0 + cb0;
                float v01 = acc[mi][ni][1] + rb0 + cb1;
                float v10 = acc[mi][ni][2] + rb1 + cb0;
                float v11 = acc[mi][ni][3] + rb1 + cb1;
                if (Cf) {
                    float* Cb = Cf + (size_t)bz * sC;
                    if (resid) {
                        const float* Rb = resid + (size_t)bz * sR;
                        float2 r0 = *(const float2*)(Rb + (size_t)row0 * ldc + col);
                        float2 r1 = *(const float2*)(Rb + (size_t)row1 * ldc + col);
                        v00 += r0.x; v01 += r0.y; v10 += r1.x; v11 += r1.y;
                    }
                    *(float2*)(Cb + (size_t)row0 * ldc + col) = make_float2(v00, v01);
                    *(float2*)(Cb + (size_t)row1 * ldc + col) = make_float2(v10, v11);
                } else {
                    __half* Hb = Ch + (size_t)bz * sC;
                    *(__half2*)(Hb + (size_t)row0 * ldc + col) =
                        __halves2half2(__float2half_rn(v00), __float2half_rn(v01));
                    *(__half2*)(Hb + (size_t)row1 * ldc + col) =
                        __halves2half2(__float2half_rn(v10), __float2half_rn(v11));
                }
            }
        }
        __syncthreads();
    }
}

// ---- 64x64 tile kernel (single wave already; unchanged) --------------------
#define T64_SZ  (64 * LDS_ * 2)
#define STAGE64 (2 * T64_SZ)
#define SMEMB64 (NSTG * STAGE64)

__device__ __forceinline__ void ld_tile_async64(
    const __half* __restrict__ g, int ldk, uint32_t sbase, int tid) {
#pragma unroll
    for (int i = 0; i < 2; ++i) {
        int idx = tid + i * 128;
        int row = idx >> 2, ch = idx & 3;
        CP_ASYNC16(sbase + row * (LDS_ * 2) + ch * 16,
                   g + (size_t)row * ldk + ch * 8);
    }
}

__global__ __launch_bounds__(128) void hmma_nt64_kernel(
    const __half* __restrict__ A, int lda, size_t sA,
    const __half* __restrict__ Bs, int ldb, size_t sB,
    __half* __restrict__ Ch, int ldc, size_t sC,
    const float* __restrict__ bias, int bias_mode, int sBias,
    int K) {
    extern __shared__ char smem[];
    const uint32_t sb = smem_u32(smem);
    const int tid = threadIdx.x;
    const int wid = tid >> 5, lane = tid & 31;
    const int wm = wid & 1, wn = wid >> 1;
    const int bz = blockIdx.z;
    const int m0 = blockIdx.y * 64, n0 = blockIdx.x * 64;

    const __half* gA = A  + (size_t)bz * sA + (size_t)m0 * lda;
    const __half* gB = Bs + (size_t)bz * sB + (size_t)n0 * ldb;

    float acc[2][4][4] = {};
    const int nt = K >> 5;
#pragma unroll
    for (int s = 0; s < NSTG - 1; ++s) {
        if (s < nt) {
            uint32_t st = sb + s * STAGE64;
            ld_tile_async64(gA + (s << 5), lda, st,          tid);
            ld_tile_async64(gB + (s << 5), ldb, st + T64_SZ, tid);
        }
        CP_COMMIT();
    }

    const int a_m  = wm * 32 + (lane & 15);
    const int a_k  = (lane >> 4) * 8;
    const int b_nr = wn * 32 + (lane & 7) + ((lane >> 4) << 3);
    const int b_k  = ((lane >> 3) & 1) * 8;

    for (int kt = 0; kt < nt; ++kt) {
        const int pre = kt + NSTG - 1;
        if (pre < nt) {
            uint32_t st = sb + (pre & (NSTG - 1)) * STAGE64;
            ld_tile_async64(gA + (pre << 5), lda, st,          tid);
            ld_tile_async64(gB + (pre << 5), ldb, st + T64_SZ, tid);
        }
        CP_COMMIT();
        const int rem = nt - 1 - kt;
        if (rem >= NSTG - 2) { CP_WAIT2(); }
        else if (rem == 1)   { CP_WAIT1(); }
        else                 { CP_WAIT0(); }
        __syncthreads();

        const uint32_t st = sb + (kt & (NSTG - 1)) * STAGE64;
#pragma unroll
        for (int ks = 0; ks < 2; ++ks) {
            const int kk = ks * 16;
            uint32_t ah[2][4], bb[2][4];
#pragma unroll
            for (int mi = 0; mi < 2; ++mi)
                ldsm_x4(ah[mi], st + (a_m + mi * 16) * (LDS_ * 2) + (kk + a_k) * 2);
#pragma unroll
            for (int nj = 0; nj < 2; ++nj)
                ldsm_x4(bb[nj], st + T64_SZ + (b_nr + nj * 16) * (LDS_ * 2) + (kk + b_k) * 2);
#pragma unroll
            for (int mi = 0; mi < 2; ++mi)
#pragma unroll
                for (int nj = 0; nj < 2; ++nj) {
                    mma16816(acc[mi][2 * nj],     ah[mi], bb[nj][0], bb[nj][1]);
                    mma16816(acc[mi][2 * nj + 1], ah[mi], bb[nj][2], bb[nj][3]);
                }
        }
        __syncthreads();
    }

    const int r_in = lane >> 2;
    const int c_in = (lane & 3) * 2;
    const float* bp = bias ? bias + bz * sBias : nullptr;
    __half* Hb = Ch + (size_t)bz * sC;
#pragma unroll
    for (int mi = 0; mi < 2; ++mi) {
        int row0 = m0 + wm * 32 + mi * 16 + r_in;
        int row1 = row0 + 8;
        float rb0 = 0.f, rb1 = 0.f;
        if (bias_mode == 1) { rb0 = bp[row0]; rb1 = bp[row1]; }
#pragma unroll
        for (int ni = 0; ni < 4; ++ni) {
            int col = n0 + wn * 32 + ni * 8 + c_in;
            float cb0 = 0.f, cb1 = 0.f;
            if (bias_mode == 2) { cb0 = bp[col]; cb1 = bp[col + 1]; }
            float v00 = acc[mi][ni][0] + rb0 + cb0;
            float v01 = acc[mi][ni][1] + rb0 + cb1;
            float v10 = acc[mi][ni][2] + rb1 + cb0;
            float v11 = acc[mi][ni][3] + rb1 + cb1;
            *(__half2*)(Hb + (size_t)row0 * ldc + col) =
                __halves2half2(__float2half_rn(v00), __float2half_rn(v01));
            *(__half2*)(Hb + (size_t)row1 * ldc + col) =
                __halves2half2(__float2half_rn(v10), __float2half_rn(v11));
        }
    }
}

// ---------------------------------------------------------------------------
// Launch sequence
// ---------------------------------------------------------------------------
extern "C" void kernel_launch(void* const* d_in, const int* in_sizes, int n_in,
                              void* d_out, int out_size) {
    const float* x        = (const float*)d_in[0];
    const float* qkv_w    = (const float*)d_in[1];
    const float* qkv_b    = (const float*)d_in[2];
    const float* proj_w   = (const float*)d_in[3];
    const float* proj_b   = (const float*)d_in[4];
    const float* gn_scale = (const float*)d_in[5];
    const float* gn_bias  = (const float*)d_in[6];
    float* out = (float*)d_out;

    cudaFuncSetAttribute(hmma_nt_kernel, cudaFuncAttributeMaxDynamicSharedMemorySize, SMEMB);
    cudaFuncSetAttribute(hmma_nt64_kernel, cudaFuncAttributeMaxDynamicSharedMemorySize, SMEMB64);

    float *biasb, *fb;
    __half *Wh, *xTh, *xh, *khl, *kh, *kxh, *ctxh, *Mh, *Eh, *wqTh, *pwh;
    cudaGetSymbolAddress((void**)&biasb, g_biasb);
    cudaGetSymbolAddress((void**)&fb, g_fb);
    cudaGetSymbolAddress((void**)&Wh, g_Wh);
    cudaGetSymbolAddress((void**)&xTh, g_xTh);
    cudaGetSymbolAddress((void**)&xh, g_xh);
    cudaGetSymbolAddress((void**)&khl, g_khl);
    cudaGetSymbolAddress((void**)&kh, g_kh);
    cudaGetSymbolAddress((void**)&kxh, g_kxh);
    cudaGetSymbolAddress((void**)&ctxh, g_ctxh);
    cudaGetSymbolAddress((void**)&Mh, g_Mh);
    cudaGetSymbolAddress((void**)&Eh, g_Eh);
    cudaGetSymbolAddress((void**)&wqTh, g_wqTh);
    cudaGetSymbolAddress((void**)&pwh, g_pwh);

    // 1) proj_w convert (+stats zero), fused x convert/transpose/stats,
    //    weight folding (stats finalized inline), q-slab transpose
    f2h_init_kernel<<<(C_ * C_ / 4 + 255) / 256, 256>>>(proj_w, pwh, C_ * C_ / 4);
    tconv_gn_kernel<<<dim3(N_ / 64, G_, B_), 256>>>(x, xTh, xh);
    prep_w_kernel<<<B_ * O3, 128>>>(qkv_w, qkv_b, gn_scale, gn_bias);
    wqt_kernel<<<dim3(C_ / 64, C_ / 64, B_), 256>>>();
    // 2) k logits (fp16 out): k[d,n] = Wk . xT + bk  — persistent, 296 blocks
    hmma_nt_kernel<<<NSM_SLOTS, 128, SMEMB>>>(
        Wh + (size_t)C_ * C_, C_, (size_t)O3 * C_,
        xTh, C_, (size_t)N_ * C_,
        nullptr, khl, N_, (size_t)C_ * N_,
        biasb + C_, 1, O3, nullptr, 0, C_,
        N_ / 128, C_ / 128);
    // 3) softmax over tokens
    softmax_kernel<<<B_ * C_, 256>>>(khl, kh);
    // 4) kx[d,c] = k_sm . x^T   (K=4096)
    hmma_nt64_kernel<<<dim3(C_ / 64, C_ / 64, B_), 128, SMEMB64>>>(
        kh, N_, (size_t)C_ * N_,
        xh, N_, (size_t)C_ * N_,
        kxh, C_, (size_t)C_ * C_,
        nullptr, 0, 0, N_);
    // 5) ctx[d,e] = kx . Wv^T + bv[e]
    hmma_nt64_kernel<<<dim3(C_ / 64, C_ / 64, B_), 128, SMEMB64>>>(
        kxh, C_, (size_t)C_ * C_,
        Wh + (size_t)2 * C_ * C_, C_, (size_t)O3 * C_,
        ctxh, C_, (size_t)C_ * C_,
        biasb + 2 * C_, 2, O3, C_);
    // 6) M[o,d] = proj_w . ctx^T
    hmma_nt64_kernel<<<dim3(C_ / 64, C_ / 64, B_), 128, SMEMB64>>>(
        pwh, C_, 0,
        ctxh, C_, (size_t)C_ * C_,
        Mh, C_, (size_t)C_ * C_,
        nullptr, 0, 0, C_);
    // 7) E[o,c] = M . WqT^T  (= M @ Wq)
    hmma_nt64_kernel<<<dim3(C_ / 64, C_ / 64, B_), 128, SMEMB64>>>(
        Mh, C_, (size_t)C_ * C_,
        wqTh, C_, (size_t)C_ * C_,
        Eh, C_, (size_t)C_ * C_,
        nullptr, 0, 0, C_);
    // 8) fb = proj_b + M @ bq
    fb_kernel<<<B_ * C_ / 8, 256>>>(proj_b);
    // 9) out[o,n] = E . xT^T + fb[o] + x — persistent, 296 blocks
    hmma_nt_kernel<<<NSM_SLOTS, 128, SMEMB>>>(
        Eh, C_, (size_t)C_ * C_,
        xTh, C_, (size_t)N_ * C_,
        out, nullptr, N_, (size_t)C_ * N_,
        fb, 1, C_, x, (size_t)C_ * N_, C_,
        N_ / 128, C_ / 128);
}

// round 14
// speedup vs baseline: 1.1514x; 1.0374x over previous
#include <cuda_runtime.h>
#include <cuda_fp16.h>
#include <cstdint>
#include <math.h>

// Problem constants
#define B_   8
#define C_   512
#define N_   4096
#define G_   8
#define CPG  64
#define O3   1536
#define EPSV 1e-6f
#define QSCALE 0.04419417382415922f   // 512^-0.5

// ---------------------------------------------------------------------------
// PTX helpers
// ---------------------------------------------------------------------------
__device__ __forceinline__ uint32_t smem_u32(const void* p) {
    uint32_t a;
    asm("{ .reg .u64 t; cvta.to.shared.u64 t, %1; cvt.u32.u64 %0, t; }" : "=r"(a) : "l"(p));
    return a;
}
__device__ __forceinline__ void ldsm_x4(uint32_t (&r)[4], uint32_t addr) {
    asm volatile("ldmatrix.sync.aligned.m8n8.x4.shared.b16 {%0,%1,%2,%3}, [%4];"
        : "=r"(r[0]), "=r"(r[1]), "=r"(r[2]), "=r"(r[3]) : "r"(addr));
}
__device__ __forceinline__ void mma16816(float (&d)[4], const uint32_t (&a)[4],
                                         uint32_t b0, uint32_t b1) {
    asm volatile(
        "mma.sync.aligned.m16n8k16.row.col.f32.f16.f16.f32 "
        "{%0,%1,%2,%3}, {%4,%5,%6,%7}, {%8,%9}, {%0,%1,%2,%3};"
        : "+f"(d[0]), "+f"(d[1]), "+f"(d[2]), "+f"(d[3])
        : "r"(a[0]), "r"(a[1]), "r"(a[2]), "r"(a[3]), "r"(b0), "r"(b1));
}
#define CP_ASYNC16(dst, src) \
    asm volatile("cp.async.cg.shared.global [%0], [%1], 16;" :: "r"(dst), "l"(src))
#define CP_COMMIT() asm volatile("cp.async.commit_group;" ::: "memory")
#define CP_WAIT0()  asm volatile("cp.async.wait_group 0;" ::: "memory")
#define CP_WAIT1()  asm volatile("cp.async.wait_group 1;" ::: "memory")
#define CP_WAIT2()  asm volatile("cp.async.wait_group 2;" ::: "memory")

#define NSM_SLOTS 296     // 2 blocks/SM x 148 SMs (persistent grid for big GEMM)

// ---------------------------------------------------------------------------
// Scratch
// ---------------------------------------------------------------------------
__device__ __half g_Wh[(size_t)B_ * O3 * C_];
__device__ float  g_biasb[B_ * O3];
__device__ float  g_ssum[B_ * G_], g_ssq[B_ * G_];
__device__ __half g_xTh[(size_t)B_ * N_ * C_];        // x token-major fp16
__device__ __half g_xh [(size_t)B_ * C_ * N_];        // x channel-major fp16
__device__ __half g_khl[(size_t)B_ * C_ * N_];        // k logits fp16
__device__ __half g_kh[(size_t)B_ * C_ * N_];         // softmaxed k fp16
__device__ __half g_kxh[(size_t)B_ * C_ * C_];        // k_sm @ x^T
__device__ __half g_ctxh[(size_t)B_ * C_ * C_];
__device__ __half g_Mh[(size_t)B_ * C_ * C_];
__device__ __half g_Eh[(size_t)B_ * C_ * C_];         // M @ Wq
__device__ __half g_wqTh[(size_t)B_ * C_ * C_];       // Wq transposed [c,o]
__device__ __half g_pwh[C_ * C_];
__device__ float  g_fb[B_ * C_];                      // final fused bias

// ---------------------------------------------------------------------------
// Reductions
// ---------------------------------------------------------------------------
__device__ __forceinline__ float warp_sum(float v) {
#pragma unroll
    for (int o = 16; o > 0; o >>= 1) v += __shfl_xor_sync(0xffffffffu, v, o);
    return v;
}
__device__ __forceinline__ float warp_max(float v) {
#pragma unroll
    for (int o = 16; o > 0; o >>= 1) v = fmaxf(v, __shfl_xor_sync(0xffffffffu, v, o));
    return v;
}
__device__ __forceinline__ float block_sum(float v, float* sh) {
    int tid = threadIdx.x, nw = blockDim.x >> 5;
    __syncthreads();
    v = warp_sum(v);
    if ((tid & 31) == 0) sh[tid >> 5] = v;
    __syncthreads();
    if (tid < 32) {
        float w = (tid < nw) ? sh[tid] : 0.f;
        w = warp_sum(w);
        if (tid == 0) sh[0] = w;
    }
    __syncthreads();
    return sh[0];
}
__device__ __forceinline__ float block_max(float v, float* sh) {
    int tid = threadIdx.x, nw = blockDim.x >> 5;
    __syncthreads();
    v = warp_max(v);
    if ((tid & 31) == 0) sh[tid >> 5] = v;
    __syncthreads();
    if (tid < 32) {
        float w = (tid < nw) ? sh[tid] : -3.402823466e38f;
        w = warp_max(w);
        if (tid == 0) sh[0] = w;
    }
    __syncthreads();
    return sh[0];
}

// GN stats -> (mean, rstd) on the fly
__device__ __forceinline__ void gn_ms(int bg, float* mean, float* rstd) {
    const float inv = 1.f / (float)(CPG * N_);
    float m = g_ssum[bg] * inv;
    *mean = m;
    *rstd = rsqrtf(g_ssq[bg] * inv - m * m + EPSV);
}

// ---------------------------------------------------------------------------
// fp32 -> fp16 convert (proj_w) + stats zero-init + fb seed (proj_b)
// ---------------------------------------------------------------------------
__global__ __launch_bounds__(256) void f2h_init_kernel(
    const float* __restrict__ in, __half* __restrict__ out, size_t n4,
    const float* __restrict__ proj_b) {
    int gt = blockIdx.x * 256 + threadIdx.x;
    if (gt < B_ * G_) { g_ssum[gt] = 0.f; g_ssq[gt] = 0.f; }
    if (gt < B_ * C_) g_fb[gt] = proj_b[gt & (C_ - 1)];
    size_t i = (size_t)gt;
    if (i >= n4) return;
    float4 v = ((const float4*)in)[i];
    __half2* o = (__half2*)(out + i * 4);
    o[0] = __halves2half2(__float2half_rn(v.x), __float2half_rn(v.y));
    o[1] = __halves2half2(__float2half_rn(v.z), __float2half_rn(v.w));
}

// ---------------------------------------------------------------------------
// Fused: x [C,N] fp32 -> xh (fp16 same layout) + xT [N,C] fp16 + GN stats.
// grid (N/64, G, B), block 256.
// ---------------------------------------------------------------------------
__global__ __launch_bounds__(256) void tconv_gn_kernel(
    const float* __restrict__ in, __half* __restrict__ outT,
    __half* __restrict__ outCh) {
    __shared__ float t[64][65];
    __shared__ float sh[32];
    int b = blockIdx.z, g = blockIdx.y;
    int n0 = blockIdx.x * 64, c0 = g * 64;
    const float* ip = in + (size_t)b * C_ * N_;
    __half* chp = outCh + (size_t)b * C_ * N_;
    int tid = threadIdx.x;
    int f4 = tid & 15, cr = tid >> 4;
    float s = 0.f, ss = 0.f;
#pragma unroll
    for (int p = 0; p < 4; ++p) {
        int c = cr + p * 16;
        float4 v = *(const float4*)(ip + (size_t)(c0 + c) * N_ + n0 + f4 * 4);
        s += v.x + v.y + v.z + v.w;
        ss = fmaf(v.x, v.x, fmaf(v.y, v.y, fmaf(v.z, v.z, fmaf(v.w, v.w, ss))));
        __half2 h01 = __halves2half2(__float2half_rn(v.x), __float2half_rn(v.y));
        __half2 h23 = __halves2half2(__float2half_rn(v.z), __float2half_rn(v.w));
        uint2 hw;
        hw.x = *(uint32_t*)&h01;
        hw.y = *(uint32_t*)&h23;
        *(uint2*)(chp + (size_t)(c0 + c) * N_ + n0 + f4 * 4) = hw;
        t[c][f4 * 4 + 0] = v.x; t[c][f4 * 4 + 1] = v.y;
        t[c][f4 * 4 + 2] = v.z; t[c][f4 * 4 + 3] = v.w;
    }
    float bs  = block_sum(s, sh);
    float bss = block_sum(ss, sh);
    if (tid == 0) {
        atomicAdd(&g_ssum[b * G_ + g], bs);
        atomicAdd(&g_ssq [b * G_ + g], bss);
    }
    __half* op = outT + (size_t)b * N_ * C_;
    int c8 = (tid & 7) * 8, nr = tid >> 3;
#pragma unroll
    for (int p = 0; p < 2; ++p) {
        int n = nr + p * 32;
        __half2 h0 = __halves2half2(__float2half_rn(t[c8 + 0][n]),
                                    __float2half_rn(t[c8 + 1][n]));
        __half2 h1 = __halves2half2(__float2half_rn(t[c8 + 2][n]),
                                    __float2half_rn(t[c8 + 3][n]));
        __half2 h2 = __halves2half2(__float2half_rn(t[c8 + 4][n]),
                                    __float2half_rn(t[c8 + 5][n]));
        __half2 h3 = __halves2half2(__float2half_rn(t[c8 + 6][n]),
                                    __float2half_rn(t[c8 + 7][n]));
        uint4 w;
        w.x = *(uint32_t*)&h0; w.y = *(uint32_t*)&h1;
        w.z = *(uint32_t*)&h2; w.w = *(uint32_t*)&h3;
        *(uint4*)(op + (size_t)(n0 + n) * C_ + c0 + c8) = w;
    }
}

// ---------------------------------------------------------------------------
// prep_w v3: one block per output row o; weights read ONCE; batch-independent
// partial sums S0 = sum_c w*gn_bias, Sg = sum_{c in g} w*gn_scale (warp==group)
//   biasb[b,o] = qs*(qkv_b[o] + S0 - sum_g (mean*rstd)_{b,g} * Sg[g])
//   Wh[b,o,c]  = rn(w * rstd_{b,g} * gn_scale[c] * qs)
// grid O3, block 256 (thread t owns c = 2t, 2t+1; warp w == group w).
// ---------------------------------------------------------------------------
__global__ __launch_bounds__(256) void prep_w_kernel(
    const float* __restrict__ qkv_w, const float* __restrict__ qkv_b,
    const float* __restrict__ gn_scale, const float* __restrict__ gn_bias) {
    int o = blockIdx.x;
    float qs = (o < C_) ? QSCALE : 1.f;
    int t = threadIdx.x, lane = t & 31, w = t >> 5;

    float2 wv = ((const float2*)(qkv_w + (size_t)o * C_))[t];
    float2 sv = ((const float2*)gn_scale)[t];
    float2 bv = ((const float2*)gn_bias)[t];

    float ws = wv.x * sv.x + wv.y * sv.y;     // -> Sg (this warp's group)
    float wb = wv.x * bv.x + wv.y * bv.y;     // -> S0
    ws = warp_sum(ws);
    wb = warp_sum(wb);

    __shared__ float shWS[8], shWB[8];
    __shared__ float shMR[B_ * G_];           // mean*rstd
    __shared__ float shR [B_ * G_];           // rstd
    if (lane == 0) { shWS[w] = ws; shWB[w] = wb; }
    if (t < B_ * G_) {
        float m, r;
        gn_ms(t, &m, &r);
        shMR[t] = m * r;
        shR[t]  = r;
    }
    __syncthreads();

    if (t < B_) {
        float S0 = 0.f, term = 0.f;
#pragma unroll
        for (int g = 0; g < 8; ++g) {
            S0   += shWB[g];
            term += shMR[t * G_ + g] * shWS[g];
        }
        g_biasb[t * O3 + o] = qs * (qkv_b[o] + S0 - term);
    }

#pragma unroll
    for (int b = 0; b < B_; ++b) {
        float r = shR[b * G_ + w];
        __half2 h = __halves2half2(__float2half_rn(wv.x * (r * sv.x * qs)),
                                   __float2half_rn(wv.y * (r * sv.y * qs)));
        *(__half2*)(g_Wh + ((size_t)b * O3 + o) * C_ + t * 2) = h;
    }
}

// ---------------------------------------------------------------------------
// Transpose q-slab of folded weights: Wq [o,c] -> wqT [c,o]  (fp16)
// ---------------------------------------------------------------------------
__global__ __launch_bounds__(256) void wqt_kernel() {
    __shared__ __half t[64][70];
    int b = blockIdx.z;
    const __half* W = g_Wh + (size_t)b * O3 * C_;
    __half* outp = g_wqTh + (size_t)b * C_ * C_;
    int c0 = blockIdx.x * 64, o0 = blockIdx.y * 64;
    int tid = threadIdx.x;
    int q = tid & 15, r = tid >> 4;
#pragma unroll
    for (int p = 0; p < 4; ++p) {
        int o = r + p * 16;
        uint2 v = *(const uint2*)(W + (size_t)(o0 + o) * C_ + c0 + q * 4);
        __half2 h01 = *(__half2*)&v.x;
        __half2 h23 = *(__half2*)&v.y;
        t[o][q * 4 + 0] = __low2half(h01); t[o][q * 4 + 1] = __high2half(h01);
        t[o][q * 4 + 2] = __low2half(h23); t[o][q * 4 + 3] = __high2half(h23);
    }
    __syncthreads();
#pragma unroll
    for (int p = 0; p < 4; ++p) {
        int c = r + p * 16;
        __half2 a = __halves2half2(t[q * 4 + 0][c], t[q * 4 + 1][c]);
        __half2 d = __halves2half2(t[q * 4 + 2][c], t[q * 4 + 3][c]);
        uint2 w;
        w.x = *(uint32_t*)&a;
        w.y = *(uint32_t*)&d;
        *(uint2*)(outp + (size_t)(c0 + c) * C_ + o0 + q * 4) = w;
    }
}

// ---------------------------------------------------------------------------
// Row softmax: fp16 logits -> fp16 probabilities (fp32 math inside)
// ---------------------------------------------------------------------------
__global__ __launch_bounds__(256) void softmax_kernel(
    const __half* __restrict__ kl, __half* __restrict__ kh) {
    int row = blockIdx.x;
    const __half2* p = (const __half2*)(kl + (size_t)row * N_);
    __half2* o = (__half2*)(kh + (size_t)row * N_);
    const int tid = threadIdx.x;
    float2 v[8];
    float mx = -3.402823466e38f;
#pragma unroll
    for (int i = 0; i < 8; i++) {
        v[i] = __half22float2(p[tid + i * 256]);
        mx = fmaxf(mx, fmaxf(v[i].x, v[i].y));
    }
    __shared__ float sh[32];
    mx = block_max(mx, sh);
    float s = 0.f;
#pragma unroll
    for (int i = 0; i < 8; i++) {
        v[i].x = __expf(v[i].x - mx); v[i].y = __expf(v[i].y - mx);
        s += v[i].x + v[i].y;
    }
    s = block_sum(s, sh);
    float inv = 1.f / s;
#pragma unroll
    for (int i = 0; i < 8; i++) {
        o[tid + i * 256] = __halves2half2(__float2half_rn(v[i].x * inv),
                                          __float2half_rn(v[i].y * inv));
    }
}

// ---------------------------------------------------------------------------
// Shared GEMM plumbing
// ---------------------------------------------------------------------------
#define LDS_   40
#define NSTG   4

// ---- 128x128 tile PERSISTENT kernel --------------------------------------
#define T_SZ   (128 * LDS_ * 2)
#define STAGE  (2 * T_SZ)
#define SMEMB  (NSTG * STAGE)

__device__ __forceinline__ void ld_tile_async128(
    const __half* __restrict__ g, int ldk, uint32_t sbase, int tid) {
#pragma unroll
    for (int i = 0; i < 4; ++i) {
        int idx = tid + i * 128;
        int row = idx >> 2, ch = idx & 3;
        CP_ASYNC16(sbase + row * (LDS_ * 2) + ch * 16,
                   g + (size_t)row * ldk + ch * 8);
    }
}

__global__ __launch_bounds__(128) void hmma_nt_kernel(
    const __half* __restrict__ A, int lda, size_t sA,
    const __half* __restrict__ Bs, int ldb, size_t sB,
    float* __restrict__ Cf, __half* __restrict__ Ch, int ldc, size_t sC,
    const float* __restrict__ bias, int bias_mode, int sBias,
    const float* __restrict__ resid, size_t sR,
    int K, int ntx, int nty) {
    extern __shared__ char smem[];
    const uint32_t sb = smem_u32(smem);
    const int tid = threadIdx.x;
    const int wid = tid >> 5, lane = tid & 31;
    const int wm = wid & 1, wn = wid >> 1;
    const int nt = K >> 5;

    const int a_m  = wm * 64 + (lane & 15);
    const int a_k  = (lane >> 4) * 8;
    const int b_nr = wn * 64 + (lane & 7) + ((lane >> 4) << 3);
    const int b_k  = ((lane >> 3) & 1) * 8;
    const int r_in = lane >> 2;
    const int c_in = (lane & 3) * 2;

    const int tiles_per_b = ntx * nty;
    const int tot = tiles_per_b * B_;

    for (int t = blockIdx.x; t < tot; t += gridDim.x) {
        const int bz = t / tiles_per_b;
        const int rem = t - bz * tiles_per_b;
        const int by = rem / ntx;
        const int bx = rem - by * ntx;
        const int m0 = by * 128, n0 = bx * 128;

        const __half* gA = A  + (size_t)bz * sA + (size_t)m0 * lda;
        const __half* gB = Bs + (size_t)bz * sB + (size_t)n0 * ldb;

        float acc[4][8][4] = {};
#pragma unroll
        for (int s = 0; s < NSTG - 1; ++s) {
            if (s < nt) {
                uint32_t st = sb + s * STAGE;
                ld_tile_async128(gA + (s << 5), lda, st,        tid);
                ld_tile_async128(gB + (s << 5), ldb, st + T_SZ, tid);
            }
            CP_COMMIT();
        }

        for (int kt = 0; kt < nt; ++kt) {
            const int pre = kt + NSTG - 1;
            if (pre < nt) {
                uint32_t st = sb + (pre & (NSTG - 1)) * STAGE;
                ld_tile_async128(gA + (pre << 5), lda, st,        tid);
                ld_tile_async128(gB + (pre << 5), ldb, st + T_SZ, tid);
            }
            CP_COMMIT();
            const int rm = nt - 1 - kt;
            if (rm >= NSTG - 2) { CP_WAIT2(); }
            else if (rm == 1)   { CP_WAIT1(); }
            else                { CP_WAIT0(); }
            __syncthreads();

            const uint32_t st = sb + (kt & (NSTG - 1)) * STAGE;
#pragma unroll
            for (int ks = 0; ks < 2; ++ks) {
                const int kk = ks * 16;
                uint32_t ah[4][4], bb[4][4];
#pragma unroll
                for (int mi = 0; mi < 4; ++mi)
                    ldsm_x4(ah[mi], st + (a_m + mi * 16) * (LDS_ * 2) + (kk + a_k) * 2);
#pragma unroll
                for (int nj = 0; nj < 4; ++nj)
                    ldsm_x4(bb[nj], st + T_SZ + (b_nr + nj * 16) * (LDS_ * 2) + (kk + b_k) * 2);
#pragma unroll
                for (int mi = 0; mi < 4; ++mi)
#pragma unroll
                    for (int nj = 0; nj < 4; ++nj) {
                        mma16816(acc[mi][2 * nj],     ah[mi], bb[nj][0], bb[nj][1]);
                        mma16816(acc[mi][2 * nj + 1], ah[mi], bb[nj][2], bb[nj][3]);
                    }
            }
            __syncthreads();
        }

        const float* bp = bias ? bias + bz * sBias : nullptr;
#pragma unroll
        for (int mi = 0; mi < 4; ++mi) {
            int row0 = m0 + wm * 64 + mi * 16 + r_in;
            int row1 = row0 + 8;
            float rb0 = 0.f, rb1 = 0.f;
            if (bias_mode == 1) { rb0 = bp[row0]; rb1 = bp[row1]; }
#pragma unroll
            for (int ni = 0; ni < 8; ++ni) {
                int col = n0 + wn * 64 + ni * 8 + c_in;
                float cb0 = 0.f, cb1 = 0.f;
                if (bias_mode == 2) { cb0 = bp[col]; cb1 = bp[col + 1]; }
                float v00 = acc[mi][ni][0] + rb0 + cb0;
                float v01 = acc[mi][ni][1] + rb0 + cb1;
                float v10 = acc[mi][ni][2] + rb1 + cb0;
                float v11 = acc[mi][ni][3] + rb1 + cb1;
                if (Cf) {
                    float* Cb = Cf + (size_t)bz * sC;
                    if (resid) {
                        const float* Rb = resid + (size_t)bz * sR;
                        float2 r0 = *(const float2*)(Rb + (size_t)row0 * ldc + col);
                        float2 r1 = *(const float2*)(Rb + (size_t)row1 * ldc + col);
                        v00 += r0.x; v01 += r0.y; v10 += r1.x; v11 += r1.y;
                    }
                    *(float2*)(Cb + (size_t)row0 * ldc + col) = make_float2(v00, v01);
                    *(float2*)(Cb + (size_t)row1 * ldc + col) = make_float2(v10, v11);
                } else {
                    __half* Hb = Ch + (size_t)bz * sC;
                    *(__half2*)(Hb + (size_t)row0 * ldc + col) =
                        __halves2half2(__float2half_rn(v00), __float2half_rn(v01));
                    *(__half2*)(Hb + (size_t)row1 * ldc + col) =
                        __halves2half2(__float2half_rn(v10), __float2half_rn(v11));
                }
            }
        }
        __syncthreads();
    }
}

// ---- 64x64 tile kernel; optional fused row-dot (fb) accumulation ----------
#define T64_SZ  (64 * LDS_ * 2)
#define STAGE64 (2 * T64_SZ)
#define SMEMB64 (NSTG * STAGE64)

__device__ __forceinline__ void ld_tile_async64(
    const __half* __restrict__ g, int ldk, uint32_t sbase, int tid) {
#pragma unroll
    for (int i = 0; i < 2; ++i) {
        int idx = tid + i * 128;
        int row = idx >> 2, ch = idx & 3;
        CP_ASYNC16(sbase + row * (LDS_ * 2) + ch * 16,
                   g + (size_t)row * ldk + ch * 8);
    }
}

__global__ __launch_bounds__(128) void hmma_nt64_kernel(
    const __half* __restrict__ A, int lda, size_t sA,
    const __half* __restrict__ Bs, int ldb, size_t sB,
    __half* __restrict__ Ch, int ldc, size_t sC,
    const float* __restrict__ bias, int bias_mode, int sBias,
    const float* __restrict__ bqv, int sBq, float* __restrict__ fbout,
    int K) {
    extern __shared__ char smem[];
    const uint32_t sb = smem_u32(smem);
    const int tid = threadIdx.x;
    const int wid = tid >> 5, lane = tid & 31;
    const int wm = wid & 1, wn = wid >> 1;
    const int bz = blockIdx.z;
    const int m0 = blockIdx.y * 64, n0 = blockIdx.x * 64;

    const __half* gA = A  + (size_t)bz * sA + (size_t)m0 * lda;
    const __half* gB = Bs + (size_t)bz * sB + (size_t)n0 * ldb;

    float acc[2][4][4] = {};
    const int nt = K >> 5;
#pragma unroll
    for (int s = 0; s < NSTG - 1; ++s) {
        if (s < nt) {
            uint32_t st = sb + s * STAGE64;
            ld_tile_async64(gA + (s << 5), lda, st,          tid);
            ld_tile_async64(gB + (s << 5), ldb, st + T64_SZ, tid);
        }
        CP_COMMIT();
    }

    const int a_m  = wm * 32 + (lane & 15);
    const int a_k  = (lane >> 4) * 8;
    const int b_nr = wn * 32 + (lane & 7) + ((lane >> 4) << 3);
    const int b_k  = ((lane >> 3) & 1) * 8;

    for (int kt = 0; kt < nt; ++kt) {
        const int pre = kt + NSTG - 1;
        if (pre < nt) {
            uint32_t st = sb + (pre & (NSTG - 1)) * STAGE64;
            ld_tile_async64(gA + (pre << 5), lda, st,          tid);
            ld_tile_async64(gB + (pre << 5), ldb, st + T64_SZ, tid);
        }
        CP_COMMIT();
        const int rem = nt - 1 - kt;
        if (rem >= NSTG - 2) { CP_WAIT2(); }
        else if (rem == 1)   { CP_WAIT1(); }
        else                 { CP_WAIT0(); }
        __syncthreads();

        const uint32_t st = sb + (kt & (NSTG - 1)) * STAGE64;
#pragma unroll
        for (int ks = 0; ks < 2; ++ks) {
            const int kk = ks * 16;
            uint32_t ah[2][4], bb[2][4];
#pragma unroll
            for (int mi = 0; mi < 2; ++mi)
                ldsm_x4(ah[mi], st + (a_m + mi * 16) * (LDS_ * 2) + (kk + a_k) * 2);
#pragma unroll
            for (int nj = 0; nj < 2; ++nj)
                ldsm_x4(bb[nj], st + T64_SZ + (b_nr + nj * 16) * (LDS_ * 2) + (kk + b_k) * 2);
#pragma unroll
            for (int mi = 0; mi < 2; ++mi)
#pragma unroll
                for (int nj = 0; nj < 2; ++nj) {
                    mma16816(acc[mi][2 * nj],     ah[mi], bb[nj][0], bb[nj][1]);
                    mma16816(acc[mi][2 * nj + 1], ah[mi], bb[nj][2], bb[nj][3]);
                }
        }
        __syncthreads();
    }

    const int r_in = lane >> 2;
    const int c_in = (lane & 3) * 2;
    const float* bp = bias ? bias + bz * sBias : nullptr;
    const float* bq = bqv ? bqv + bz * sBq : nullptr;
    __half* Hb = Ch + (size_t)bz * sC;
#pragma unroll
    for (int mi = 0; mi < 2; ++mi) {
        int row0 = m0 + wm * 32 + mi * 16 + r_in;
        int row1 = row0 + 8;
        float rb0 = 0.f, rb1 = 0.f;
        if (bias_mode == 1) { rb0 = bp[row0]; rb1 = bp[row1]; }
        float pr0 = 0.f, pr1 = 0.f;
#pragma unroll
        for (int ni = 0; ni < 4; ++ni) {
            int col = n0 + wn * 32 + ni * 8 + c_in;
            float cb0 = 0.f, cb1 = 0.f;
            if (bias_mode == 2) { cb0 = bp[col]; cb1 = bp[col + 1]; }
            float v00 = acc[mi][ni][0] + rb0 + cb0;
            float v01 = acc[mi][ni][1] + rb0 + cb1;
            float v10 = acc[mi][ni][2] + rb1 + cb0;
            float v11 = acc[mi][ni][3] + rb1 + cb1;
            if (bq) {
                float q0 = bq[col], q1 = bq[col + 1];
                pr0 = fmaf(v00, q0, fmaf(v01, q1, pr0));
                pr1 = fmaf(v10, q0, fmaf(v11, q1, pr1));
            }
            *(__half2*)(Hb + (size_t)row0 * ldc + col) =
                __halves2half2(__float2half_rn(v00), __float2half_rn(v01));
            *(__half2*)(Hb + (size_t)row1 * ldc + col) =
                __halves2half2(__float2half_rn(v10), __float2half_rn(v11));
        }
        if (bq) {
            pr0 += __shfl_xor_sync(0xffffffffu, pr0, 1);
            pr0 += __shfl_xor_sync(0xffffffffu, pr0, 2);
            pr1 += __shfl_xor_sync(0xffffffffu, pr1, 1);
            pr1 += __shfl_xor_sync(0xffffffffu, pr1, 2);
            if ((lane & 3) == 0) {
                atomicAdd(&fbout[bz * C_ + row0], pr0);
                atomicAdd(&fbout[bz * C_ + row1], pr1);
            }
        }
    }
}

// ---------------------------------------------------------------------------
// Launch sequence
// ---------------------------------------------------------------------------
extern "C" void kernel_launch(void* const* d_in, const int* in_sizes, int n_in,
                              void* d_out, int out_size) {
    const float* x        = (const float*)d_in[0];
    const float* qkv_w    = (const float*)d_in[1];
    const float* qkv_b    = (const float*)d_in[2];
    const float* proj_w   = (const float*)d_in[3];
    const float* proj_b   = (const float*)d_in[4];
    const float* gn_scale = (const float*)d_in[5];
    const float* gn_bias  = (const float*)d_in[6];
    float* out = (float*)d_out;

    cudaFuncSetAttribute(hmma_nt_kernel, cudaFuncAttributeMaxDynamicSharedMemorySize, SMEMB);
    cudaFuncSetAttribute(hmma_nt64_kernel, cudaFuncAttributeMaxDynamicSharedMemorySize, SMEMB64);

    float *biasb, *fb;
    __half *Wh, *xTh, *xh, *khl, *kh, *kxh, *ctxh, *Mh, *Eh, *wqTh, *pwh;
    cudaGetSymbolAddress((void**)&biasb, g_biasb);
    cudaGetSymbolAddress((void**)&fb, g_fb);
    cudaGetSymbolAddress((void**)&Wh, g_Wh);
    cudaGetSymbolAddress((void**)&xTh, g_xTh);
    cudaGetSymbolAddress((void**)&xh, g_xh);
    cudaGetSymbolAddress((void**)&khl, g_khl);
    cudaGetSymbolAddress((void**)&kh, g_kh);
    cudaGetSymbolAddress((void**)&kxh, g_kxh);
    cudaGetSymbolAddress((void**)&ctxh, g_ctxh);
    cudaGetSymbolAddress((void**)&Mh, g_Mh);
    cudaGetSymbolAddress((void**)&Eh, g_Eh);
    cudaGetSymbolAddress((void**)&wqTh, g_wqTh);
    cudaGetSymbolAddress((void**)&pwh, g_pwh);

    // 1) proj_w convert (+stats zero, +fb seed), fused x convert/transpose/
    //    stats, weight folding (stats inline), q-slab transpose
    f2h_init_kernel<<<(C_ * C_ / 4 + 255) / 256, 256>>>(proj_w, pwh, C_ * C_ / 4, proj_b);
    tconv_gn_kernel<<<dim3(N_ / 64, G_, B_), 256>>>(x, xTh, xh);
    prep_w_kernel<<<O3, 256>>>(qkv_w, qkv_b, gn_scale, gn_bias);
    wqt_kernel<<<dim3(C_ / 64, C_ / 64, B_), 256>>>();
    // 2) k logits (fp16 out): k[d,n] = Wk . xT + bk  — persistent
    hmma_nt_kernel<<<NSM_SLOTS, 128, SMEMB>>>(
        Wh + (size_t)C_ * C_, C_, (size_t)O3 * C_,
        xTh, C_, (size_t)N_ * C_,
        nullptr, khl, N_, (size_t)C_ * N_,
        biasb + C_, 1, O3, nullptr, 0, C_,
        N_ / 128, C_ / 128);
    // 3) softmax over tokens
    softmax_kernel<<<B_ * C_, 256>>>(khl, kh);
    // 4) kx[d,c] = k_sm . x^T   (K=4096)
    hmma_nt64_kernel<<<dim3(C_ / 64, C_ / 64, B_), 128, SMEMB64>>>(
        kh, N_, (size_t)C_ * N_,
        xh, N_, (size_t)C_ * N_,
        kxh, C_, (size_t)C_ * C_,
        nullptr, 0, 0, nullptr, 0, nullptr, N_);
    // 5) ctx[d,e] = kx . Wv^T + bv[e]
    hmma_nt64_kernel<<<dim3(C_ / 64, C_ / 64, B_), 128, SMEMB64>>>(
        kxh, C_, (size_t)C_ * C_,
        Wh + (size_t)2 * C_ * C_, C_, (size_t)O3 * C_,
        ctxh, C_, (size_t)C_ * C_,
        biasb + 2 * C_, 2, O3, nullptr, 0, nullptr, C_);
    // 6) M[o,d] = proj_w . ctx^T   (+ fused fb += M @ bq via atomics)
    hmma_nt64_kernel<<<dim3(C_ / 64, C_ / 64, B_), 128, SMEMB64>>>(
        pwh, C_, 0,
        ctxh, C_, (size_t)C_ * C_,
        Mh, C_, (size_t)C_ * C_,
        nullptr, 0, 0, biasb, O3, fb, C_);
    // 7) E[o,c] = M . WqT^T  (= M @ Wq)
    hmma_nt64_kernel<<<dim3(C_ / 64, C_ / 64, B_), 128, SMEMB64>>>(
        Mh, C_, (size_t)C_ * C_,
        wqTh, C_, (size_t)C_ * C_,
        Eh, C_, (size_t)C_ * C_,
        nullptr, 0, 0, nullptr, 0, nullptr, C_);
    // 8) out[o,n] = E . xT^T + fb[o] + x — persistent
    hmma_nt_kernel<<<NSM_SLOTS, 128, SMEMB>>>(
        Eh, C_, (size_t)C_ * C_,
        xTh, C_, (size_t)N_ * C_,
        out, nullptr, N_, (size_t)C_ * N_,
        fb, 1, C_, x, (size_t)C_ * N_, C_,
        N_ / 128, C_ / 128);
}

// round 15
// speedup vs baseline: 1.1659x; 1.0126x over previous
#include <cuda_runtime.h>
#include <cuda_fp16.h>
#include <cstdint>
#include <math.h>

// Problem constants
#define B_   8
#define C_   512
#define N_   4096
#define G_   8
#define CPG  64
#define O3   1536
#define EPSV 1e-6f
#define QSCALE 0.04419417382415922f   // 512^-0.5

// ---------------------------------------------------------------------------
// PTX helpers
// ---------------------------------------------------------------------------
__device__ __forceinline__ uint32_t smem_u32(const void* p) {
    uint32_t a;
    asm("{ .reg .u64 t; cvta.to.shared.u64 t, %1; cvt.u32.u64 %0, t; }" : "=r"(a) : "l"(p));
    return a;
}
__device__ __forceinline__ void ldsm_x4(uint32_t (&r)[4], uint32_t addr) {
    asm volatile("ldmatrix.sync.aligned.m8n8.x4.shared.b16 {%0,%1,%2,%3}, [%4];"
        : "=r"(r[0]), "=r"(r[1]), "=r"(r[2]), "=r"(r[3]) : "r"(addr));
}
__device__ __forceinline__ void mma16816(float (&d)[4], const uint32_t (&a)[4],
                                         uint32_t b0, uint32_t b1) {
    asm volatile(
        "mma.sync.aligned.m16n8k16.row.col.f32.f16.f16.f32 "
        "{%0,%1,%2,%3}, {%4,%5,%6,%7}, {%8,%9}, {%0,%1,%2,%3};"
        : "+f"(d[0]), "+f"(d[1]), "+f"(d[2]), "+f"(d[3])
        : "r"(a[0]), "r"(a[1]), "r"(a[2]), "r"(a[3]), "r"(b0), "r"(b1));
}
#define CP_ASYNC16(dst, src) \
    asm volatile("cp.async.cg.shared.global [%0], [%1], 16;" :: "r"(dst), "l"(src))
#define CP_COMMIT() asm volatile("cp.async.commit_group;" ::: "memory")
#define CP_WAIT0()  asm volatile("cp.async.wait_group 0;" ::: "memory")
#define CP_WAIT1()  asm volatile("cp.async.wait_group 1;" ::: "memory")
#define CP_WAIT2()  asm volatile("cp.async.wait_group 2;" ::: "memory")

#define NSM_SLOTS 296     // 2 blocks/SM x 148 SMs (persistent grid for big GEMM)

// ---------------------------------------------------------------------------
// Scratch
// ---------------------------------------------------------------------------
__device__ __half g_Wh[(size_t)B_ * O3 * C_];
__device__ float  g_biasb[B_ * O3];
__device__ float  g_ssum[B_ * G_], g_ssq[B_ * G_];
__device__ __half g_xTh[(size_t)B_ * N_ * C_];        // x token-major fp16
__device__ __half g_xh [(size_t)B_ * C_ * N_];        // x channel-major fp16
__device__ __half g_ekh[(size_t)B_ * C_ * N_];        // exp(k logits) fp16 (unnormalized)
__device__ float  g_zsum[B_ * C_];                    // per-row sum of exp
__device__ __half g_kxh[(size_t)B_ * C_ * C_];        // k_sm @ x^T (normalized in epilogue)
__device__ __half g_ctxh[(size_t)B_ * C_ * C_];
__device__ __half g_Mh[(size_t)B_ * C_ * C_];
__device__ __half g_Eh[(size_t)B_ * C_ * C_];         // M @ Wq
__device__ __half g_wqTh[(size_t)B_ * C_ * C_];       // Wq transposed [c,o]
__device__ __half g_pwh[C_ * C_];
__device__ float  g_fb[B_ * C_];                      // final fused bias

// ---------------------------------------------------------------------------
// Reductions
// ---------------------------------------------------------------------------
__device__ __forceinline__ float warp_sum(float v) {
#pragma unroll
    for (int o = 16; o > 0; o >>= 1) v += __shfl_xor_sync(0xffffffffu, v, o);
    return v;
}
__device__ __forceinline__ float block_sum(float v, float* sh) {
    int tid = threadIdx.x, nw = blockDim.x >> 5;
    __syncthreads();
    v = warp_sum(v);
    if ((tid & 31) == 0) sh[tid >> 5] = v;
    __syncthreads();
    if (tid < 32) {
        float w = (tid < nw) ? sh[tid] : 0.f;
        w = warp_sum(w);
        if (tid == 0) sh[0] = w;
    }
    __syncthreads();
    return sh[0];
}

// GN stats -> (mean, rstd) on the fly
__device__ __forceinline__ void gn_ms(int bg, float* mean, float* rstd) {
    const float inv = 1.f / (float)(CPG * N_);
    float m = g_ssum[bg] * inv;
    *mean = m;
    *rstd = rsqrtf(g_ssq[bg] * inv - m * m + EPSV);
}

// ---------------------------------------------------------------------------
// fp32 -> fp16 convert (proj_w) + stats zero + fb seed (proj_b) + zsum zero
// ---------------------------------------------------------------------------
__global__ __launch_bounds__(256) void f2h_init_kernel(
    const float* __restrict__ in, __half* __restrict__ out, size_t n4,
    const float* __restrict__ proj_b) {
    int gt = blockIdx.x * 256 + threadIdx.x;
    if (gt < B_ * G_) { g_ssum[gt] = 0.f; g_ssq[gt] = 0.f; }
    if (gt < B_ * C_) {
        g_fb[gt] = proj_b[gt & (C_ - 1)];
        g_zsum[gt] = 0.f;
    }
    size_t i = (size_t)gt;
    if (i >= n4) return;
    float4 v = ((const float4*)in)[i];
    __half2* o = (__half2*)(out + i * 4);
    o[0] = __halves2half2(__float2half_rn(v.x), __float2half_rn(v.y));
    o[1] = __halves2half2(__float2half_rn(v.z), __float2half_rn(v.w));
}

// ---------------------------------------------------------------------------
// Fused: x [C,N] fp32 -> xh (fp16 same layout) + xT [N,C] fp16 + GN stats.
// grid (N/64, G, B), block 256.
// ---------------------------------------------------------------------------
__global__ __launch_bounds__(256) void tconv_gn_kernel(
    const float* __restrict__ in, __half* __restrict__ outT,
    __half* __restrict__ outCh) {
    __shared__ float t[64][65];
    __shared__ float sh[32];
    int b = blockIdx.z, g = blockIdx.y;
    int n0 = blockIdx.x * 64, c0 = g * 64;
    const float* ip = in + (size_t)b * C_ * N_;
    __half* chp = outCh + (size_t)b * C_ * N_;
    int tid = threadIdx.x;
    int f4 = tid & 15, cr = tid >> 4;
    float s = 0.f, ss = 0.f;
#pragma unroll
    for (int p = 0; p < 4; ++p) {
        int c = cr + p * 16;
        float4 v = *(const float4*)(ip + (size_t)(c0 + c) * N_ + n0 + f4 * 4);
        s += v.x + v.y + v.z + v.w;
        ss = fmaf(v.x, v.x, fmaf(v.y, v.y, fmaf(v.z, v.z, fmaf(v.w, v.w, ss))));
        __half2 h01 = __halves2half2(__float2half_rn(v.x), __float2half_rn(v.y));
        __half2 h23 = __halves2half2(__float2half_rn(v.z), __float2half_rn(v.w));
        uint2 hw;
        hw.x = *(uint32_t*)&h01;
        hw.y = *(uint32_t*)&h23;
        *(uint2*)(chp + (size_t)(c0 + c) * N_ + n0 + f4 * 4) = hw;
        t[c][f4 * 4 + 0] = v.x; t[c][f4 * 4 + 1] = v.y;
        t[c][f4 * 4 + 2] = v.z; t[c][f4 * 4 + 3] = v.w;
    }
    float bs  = block_sum(s, sh);
    float bss = block_sum(ss, sh);
    if (tid == 0) {
        atomicAdd(&g_ssum[b * G_ + g], bs);
        atomicAdd(&g_ssq [b * G_ + g], bss);
    }
    __half* op = outT + (size_t)b * N_ * C_;
    int c8 = (tid & 7) * 8, nr = tid >> 3;
#pragma unroll
    for (int p = 0; p < 2; ++p) {
        int n = nr + p * 32;
        __half2 h0 = __halves2half2(__float2half_rn(t[c8 + 0][n]),
                                    __float2half_rn(t[c8 + 1][n]));
        __half2 h1 = __halves2half2(__float2half_rn(t[c8 + 2][n]),
                                    __float2half_rn(t[c8 + 3][n]));
        __half2 h2 = __halves2half2(__float2half_rn(t[c8 + 4][n]),
                                    __float2half_rn(t[c8 + 5][n]));
        __half2 h3 = __halves2half2(__float2half_rn(t[c8 + 6][n]),
                                    __float2half_rn(t[c8 + 7][n]));
        uint4 w;
        w.x = *(uint32_t*)&h0; w.y = *(uint32_t*)&h1;
        w.z = *(uint32_t*)&h2; w.w = *(uint32_t*)&h3;
        *(uint4*)(op + (size_t)(n0 + n) * C_ + c0 + c8) = w;
    }
}

// ---------------------------------------------------------------------------
// prep_w v3 (round-14 proven): one block per output row o; weights read once.
// ---------------------------------------------------------------------------
__global__ __launch_bounds__(256) void prep_w_kernel(
    const float* __restrict__ qkv_w, const float* __restrict__ qkv_b,
    const float* __restrict__ gn_scale, const float* __restrict__ gn_bias) {
    int o = blockIdx.x;
    float qs = (o < C_) ? QSCALE : 1.f;
    int t = threadIdx.x, lane = t & 31, w = t >> 5;

    float2 wv = ((const float2*)(qkv_w + (size_t)o * C_))[t];
    float2 sv = ((const float2*)gn_scale)[t];
    float2 bv = ((const float2*)gn_bias)[t];

    float ws = wv.x * sv.x + wv.y * sv.y;
    float wb = wv.x * bv.x + wv.y * bv.y;
    ws = warp_sum(ws);
    wb = warp_sum(wb);

    __shared__ float shWS[8], shWB[8];
    __shared__ float shMR[B_ * G_];
    __shared__ float shR [B_ * G_];
    if (lane == 0) { shWS[w] = ws; shWB[w] = wb; }
    if (t < B_ * G_) {
        float m, r;
        gn_ms(t, &m, &r);
        shMR[t] = m * r;
        shR[t]  = r;
    }
    __syncthreads();

    if (t < B_) {
        float S0 = 0.f, term = 0.f;
#pragma unroll
        for (int g = 0; g < 8; ++g) {
            S0   += shWB[g];
            term += shMR[t * G_ + g] * shWS[g];
        }
        g_biasb[t * O3 + o] = qs * (qkv_b[o] + S0 - term);
    }

#pragma unroll
    for (int b = 0; b < B_; ++b) {
        float r = shR[b * G_ + w];
        __half2 h = __halves2half2(__float2half_rn(wv.x * (r * sv.x * qs)),
                                   __float2half_rn(wv.y * (r * sv.y * qs)));
        *(__half2*)(g_Wh + ((size_t)b * O3 + o) * C_ + t * 2) = h;
    }
}

// ---------------------------------------------------------------------------
// Transpose q-slab of folded weights: Wq [o,c] -> wqT [c,o]  (fp16)
// ---------------------------------------------------------------------------
__global__ __launch_bounds__(256) void wqt_kernel() {
    __shared__ __half t[64][70];
    int b = blockIdx.z;
    const __half* W = g_Wh + (size_t)b * O3 * C_;
    __half* outp = g_wqTh + (size_t)b * C_ * C_;
    int c0 = blockIdx.x * 64, o0 = blockIdx.y * 64;
    int tid = threadIdx.x;
    int q = tid & 15, r = tid >> 4;
#pragma unroll
    for (int p = 0; p < 4; ++p) {
        int o = r + p * 16;
        uint2 v = *(const uint2*)(W + (size_t)(o0 + o) * C_ + c0 + q * 4);
        __half2 h01 = *(__half2*)&v.x;
        __half2 h23 = *(__half2*)&v.y;
        t[o][q * 4 + 0] = __low2half(h01); t[o][q * 4 + 1] = __high2half(h01);
        t[o][q * 4 + 2] = __low2half(h23); t[o][q * 4 + 3] = __high2half(h23);
    }
    __syncthreads();
#pragma unroll
    for (int p = 0; p < 4; ++p) {
        int c = r + p * 16;
        __half2 a = __halves2half2(t[q * 4 + 0][c], t[q * 4 + 1][c]);
        __half2 d = __halves2half2(t[q * 4 + 2][c], t[q * 4 + 3][c]);
        uint2 w;
        w.x = *(uint32_t*)&a;
        w.y = *(uint32_t*)&d;
        *(uint2*)(outp + (size_t)(c0 + c) * C_ + o0 + q * 4) = w;
    }
}

// ---------------------------------------------------------------------------
// Shared GEMM plumbing
// ---------------------------------------------------------------------------
#define LDS_   40
#define NSTG   4

// ---- 128x128 tile PERSISTENT kernel --------------------------------------
// zsum != null: epilogue applies exp() to outputs (fp16 path) and atomically
// accumulates per-row sums of exp into zsum (fused softmax numerator+Z).
#define T_SZ   (128 * LDS_ * 2)
#define STAGE  (2 * T_SZ)
#define SMEMB  (NSTG * STAGE)

__device__ __forceinline__ void ld_tile_async128(
    const __half* __restrict__ g, int ldk, uint32_t sbase, int tid) {
#pragma unroll
    for (int i = 0; i < 4; ++i) {
        int idx = tid + i * 128;
        int row = idx >> 2, ch = idx & 3;
        CP_ASYNC16(sbase + row * (LDS_ * 2) + ch * 16,
                   g + (size_t)row * ldk + ch * 8);
    }
}

__global__ __launch_bounds__(128) void hmma_nt_kernel(
    const __half* __restrict__ A, int lda, size_t sA,
    const __half* __restrict__ Bs, int ldb, size_t sB,
    float* __restrict__ Cf, __half* __restrict__ Ch, int ldc, size_t sC,
    const float* __restrict__ bias, int bias_mode, int sBias,
    const float* __restrict__ resid, size_t sR,
    float* __restrict__ zsum,
    int K, int ntx, int nty) {
    extern __shared__ char smem[];
    const uint32_t sb = smem_u32(smem);
    const int tid = threadIdx.x;
    const int wid = tid >> 5, lane = tid & 31;
    const int wm = wid & 1, wn = wid >> 1;
    const int nt = K >> 5;

    const int a_m  = wm * 64 + (lane & 15);
    const int a_k  = (lane >> 4) * 8;
    const int b_nr = wn * 64 + (lane & 7) + ((lane >> 4) << 3);
    const int b_k  = ((lane >> 3) & 1) * 8;
    const int r_in = lane >> 2;
    const int c_in = (lane & 3) * 2;

    const int tiles_per_b = ntx * nty;
    const int tot = tiles_per_b * B_;

    for (int t = blockIdx.x; t < tot; t += gridDim.x) {
        const int bz = t / tiles_per_b;
        const int rem = t - bz * tiles_per_b;
        const int by = rem / ntx;
        const int bx = rem - by * ntx;
        const int m0 = by * 128, n0 = bx * 128;

        const __half* gA = A  + (size_t)bz * sA + (size_t)m0 * lda;
        const __half* gB = Bs + (size_t)bz * sB + (size_t)n0 * ldb;

        float acc[4][8][4] = {};
#pragma unroll
        for (int s = 0; s < NSTG - 1; ++s) {
            if (s < nt) {
                uint32_t st = sb + s * STAGE;
                ld_tile_async128(gA + (s << 5), lda, st,        tid);
                ld_tile_async128(gB + (s << 5), ldb, st + T_SZ, tid);
            }
            CP_COMMIT();
        }

        for (int kt = 0; kt < nt; ++kt) {
            const int pre = kt + NSTG - 1;
            if (pre < nt) {
                uint32_t st = sb + (pre & (NSTG - 1)) * STAGE;
                ld_tile_async128(gA + (pre << 5), lda, st,        tid);
                ld_tile_async128(gB + (pre << 5), ldb, st + T_SZ, tid);
            }
            CP_COMMIT();
            const int rm = nt - 1 - kt;
            if (rm >= NSTG - 2) { CP_WAIT2(); }
            else if (rm == 1)   { CP_WAIT1(); }
            else                { CP_WAIT0(); }
            __syncthreads();

            const uint32_t st = sb + (kt & (NSTG - 1)) * STAGE;
#pragma unroll
            for (int ks = 0; ks < 2; ++ks) {
                const int kk = ks * 16;
                uint32_t ah[4][4], bb[4][4];
#pragma unroll
                for (int mi = 0; mi < 4; ++mi)
                    ldsm_x4(ah[mi], st + (a_m + mi * 16) * (LDS_ * 2) + (kk + a_k) * 2);
#pragma unroll
                for (int nj = 0; nj < 4; ++nj)
                    ldsm_x4(bb[nj], st + T_SZ + (b_nr + nj * 16) * (LDS_ * 2) + (kk + b_k) * 2);
#pragma unroll
                for (int mi = 0; mi < 4; ++mi)
#pragma unroll
                    for (int nj = 0; nj < 4; ++nj) {
                        mma16816(acc[mi][2 * nj],     ah[mi], bb[nj][0], bb[nj][1]);
                        mma16816(acc[mi][2 * nj + 1], ah[mi], bb[nj][2], bb[nj][3]);
                    }
            }
            __syncthreads();
        }

        const float* bp = bias ? bias + bz * sBias : nullptr;
#pragma unroll
        for (int mi = 0; mi < 4; ++mi) {
            int row0 = m0 + wm * 64 + mi * 16 + r_in;
            int row1 = row0 + 8;
            float rb0 = 0.f, rb1 = 0.f;
            if (bias_mode == 1) { rb0 = bp[row0]; rb1 = bp[row1]; }
            float pz0 = 0.f, pz1 = 0.f;
#pragma unroll
            for (int ni = 0; ni < 8; ++ni) {
                int col = n0 + wn * 64 + ni * 8 + c_in;
                float cb0 = 0.f, cb1 = 0.f;
                if (bias_mode == 2) { cb0 = bp[col]; cb1 = bp[col + 1]; }
                float v00 = acc[mi][ni][0] + rb0 + cb0;
                float v01 = acc[mi][ni][1] + rb0 + cb1;
                float v10 = acc[mi][ni][2] + rb1 + cb0;
                float v11 = acc[mi][ni][3] + rb1 + cb1;
                if (Cf) {
                    float* Cb = Cf + (size_t)bz * sC;
                    if (resid) {
                        const float* Rb = resid + (size_t)bz * sR;
                        float2 r0 = *(const float2*)(Rb + (size_t)row0 * ldc + col);
                        float2 r1 = *(const float2*)(Rb + (size_t)row1 * ldc + col);
                        v00 += r0.x; v01 += r0.y; v10 += r1.x; v11 += r1.y;
                    }
                    *(float2*)(Cb + (size_t)row0 * ldc + col) = make_float2(v00, v01);
                    *(float2*)(Cb + (size_t)row1 * ldc + col) = make_float2(v10, v11);
                } else {
                    if (zsum) {
                        v00 = __expf(v00); v01 = __expf(v01);
                        v10 = __expf(v10); v11 = __expf(v11);
                        pz0 += v00 + v01;
                        pz1 += v10 + v11;
                    }
                    __half* Hb = Ch + (size_t)bz * sC;
                    *(__half2*)(Hb + (size_t)row0 * ldc + col) =
                        __halves2half2(__float2half_rn(v00), __float2half_rn(v01));
                    *(__half2*)(Hb + (size_t)row1 * ldc + col) =
                        __halves2half2(__float2half_rn(v10), __float2half_rn(v11));
                }
            }
            if (zsum) {
                pz0 += __shfl_xor_sync(0xffffffffu, pz0, 1);
                pz0 += __shfl_xor_sync(0xffffffffu, pz0, 2);
                pz1 += __shfl_xor_sync(0xffffffffu, pz1, 1);
                pz1 += __shfl_xor_sync(0xffffffffu, pz1, 2);
                if ((lane & 3) == 0) {
                    atomicAdd(&zsum[bz * C_ + row0], pz0);
                    atomicAdd(&zsum[bz * C_ + row1], pz1);
                }
            }
        }
        __syncthreads();
    }
}

// ---- 64x64 tile kernel; optional row-divide (softmax Z) and fused fb ------
#define T64_SZ  (64 * LDS_ * 2)
#define STAGE64 (2 * T64_SZ)
#define SMEMB64 (NSTG * STAGE64)

__device__ __forceinline__ void ld_tile_async64(
    const __half* __restrict__ g, int ldk, uint32_t sbase, int tid) {
#pragma unroll
    for (int i = 0; i < 2; ++i) {
        int idx = tid + i * 128;
        int row = idx >> 2, ch = idx & 3;
        CP_ASYNC16(sbase + row * (LDS_ * 2) + ch * 16,
                   g + (size_t)row * ldk + ch * 8);
    }
}

__global__ __launch_bounds__(128) void hmma_nt64_kernel(
    const __half* __restrict__ A, int lda, size_t sA,
    const __half* __restrict__ Bs, int ldb, size_t sB,
    __half* __restrict__ Ch, int ldc, size_t sC,
    const float* __restrict__ bias, int bias_mode, int sBias,
    const float* __restrict__ bqv, int sBq, float* __restrict__ fbout,
    const float* __restrict__ rowdiv,
    int K) {
    extern __shared__ char smem[];
    const uint32_t sb = smem_u32(smem);
    const int tid = threadIdx.x;
    const int wid = tid >> 5, lane = tid & 31;
    const int wm = wid & 1, wn = wid >> 1;
    const int bz = blockIdx.z;
    const int m0 = blockIdx.y * 64, n0 = blockIdx.x * 64;

    const __half* gA = A  + (size_t)bz * sA + (size_t)m0 * lda;
    const __half* gB = Bs + (size_t)bz * sB + (size_t)n0 * ldb;

    float acc[2][4][4] = {};
    const int nt = K >> 5;
#pragma unroll
    for (int s = 0; s < NSTG - 1; ++s) {
        if (s < nt) {
            uint32_t st = sb + s * STAGE64;
            ld_tile_async64(gA + (s << 5), lda, st,          tid);
            ld_tile_async64(gB + (s << 5), ldb, st + T64_SZ, tid);
        }
        CP_COMMIT();
    }

    const int a_m  = wm * 32 + (lane & 15);
    const int a_k  = (lane >> 4) * 8;
    const int b_nr = wn * 32 + (lane & 7) + ((lane >> 4) << 3);
    const int b_k  = ((lane >> 3) & 1) * 8;

    for (int kt = 0; kt < nt; ++kt) {
        const int pre = kt + NSTG - 1;
        if (pre < nt) {
            uint32_t st = sb + (pre & (NSTG - 1)) * STAGE64;
            ld_tile_async64(gA + (pre << 5), lda, st,          tid);
            ld_tile_async64(gB + (pre << 5), ldb, st + T64_SZ, tid);
        }
        CP_COMMIT();
        const int rem = nt - 1 - kt;
        if (rem >= NSTG - 2) { CP_WAIT2(); }
        else if (rem == 1)   { CP_WAIT1(); }
        else                 { CP_WAIT0(); }
        __syncthreads();

        const uint32_t st = sb + (kt & (NSTG - 1)) * STAGE64;
#pragma unroll
        for (int ks = 0; ks < 2; ++ks) {
            const int kk = ks * 16;
            uint32_t ah[2][4], bb[2][4];
#pragma unroll
            for (int mi = 0; mi < 2; ++mi)
                ldsm_x4(ah[mi], st + (a_m + mi * 16) * (LDS_ * 2) + (kk + a_k) * 2);
#pragma unroll
            for (int nj = 0; nj < 2; ++nj)
                ldsm_x4(bb[nj], st + T64_SZ + (b_nr + nj * 16) * (LDS_ * 2) + (kk + b_k) * 2);
#pragma unroll
            for (int mi = 0; mi < 2; ++mi)
#pragma unroll
                for (int nj = 0; nj < 2; ++nj) {
                    mma16816(acc[mi][2 * nj],     ah[mi], bb[nj][0], bb[nj][1]);
                    mma16816(acc[mi][2 * nj + 1], ah[mi], bb[nj][2], bb[nj][3]);
                }
        }
        __syncthreads();
    }

    const int r_in = lane >> 2;
    const int c_in = (lane & 3) * 2;
    const float* bp = bias ? bias + bz * sBias : nullptr;
    const float* bq = bqv ? bqv + bz * sBq : nullptr;
    const float* rd = rowdiv ? rowdiv + bz * C_ : nullptr;
    __half* Hb = Ch + (size_t)bz * sC;
#pragma unroll
    for (int mi = 0; mi < 2; ++mi) {
        int row0 = m0 + wm * 32 + mi * 16 + r_in;
        int row1 = row0 + 8;
        float rb0 = 0.f, rb1 = 0.f;
        if (bias_mode == 1) { rb0 = bp[row0]; rb1 = bp[row1]; }
        float rs0 = 1.f, rs1 = 1.f;
        if (rd) { rs0 = 1.f / rd[row0]; rs1 = 1.f / rd[row1]; }
        float pr0 = 0.f, pr1 = 0.f;
#pragma unroll
        for (int ni = 0; ni < 4; ++ni) {
            int col = n0 + wn * 32 + ni * 8 + c_in;
            float cb0 = 0.f, cb1 = 0.f;
            if (bias_mode == 2) { cb0 = bp[col]; cb1 = bp[col + 1]; }
            float v00 = acc[mi][ni][0] * rs0 + rb0 + cb0;
            float v01 = acc[mi][ni][1] * rs0 + rb0 + cb1;
            float v10 = acc[mi][ni][2] * rs1 + rb1 + cb0;
            float v11 = acc[mi][ni][3] * rs1 + rb1 + cb1;
            if (bq) {
                float q0 = bq[col], q1 = bq[col + 1];
                pr0 = fmaf(v00, q0, fmaf(v01, q1, pr0));
                pr1 = fmaf(v10, q0, fmaf(v11, q1, pr1));
            }
            *(__half2*)(Hb + (size_t)row0 * ldc + col) =
                __halves2half2(__float2half_rn(v00), __float2half_rn(v01));
            *(__half2*)(Hb + (size_t)row1 * ldc + col) =
                __halves2half2(__float2half_rn(v10), __float2half_rn(v11));
        }
        if (bq) {
            pr0 += __shfl_xor_sync(0xffffffffu, pr0, 1);
            pr0 += __shfl_xor_sync(0xffffffffu, pr0, 2);
            pr1 += __shfl_xor_sync(0xffffffffu, pr1, 1);
            pr1 += __shfl_xor_sync(0xffffffffu, pr1, 2);
            if ((lane & 3) == 0) {
                atomicAdd(&fbout[bz * C_ + row0], pr0);
                atomicAdd(&fbout[bz * C_ + row1], pr1);
            }
        }
    }
}

// ---------------------------------------------------------------------------
// Launch sequence
// ---------------------------------------------------------------------------
extern "C" void kernel_launch(void* const* d_in, const int* in_sizes, int n_in,
                              void* d_out, int out_size) {
    const float* x        = (const float*)d_in[0];
    const float* qkv_w    = (const float*)d_in[1];
    const float* qkv_b    = (const float*)d_in[2];
    const float* proj_w   = (const float*)d_in[3];
    const float* proj_b   = (const float*)d_in[4];
    const float* gn_scale = (const float*)d_in[5];
    const float* gn_bias  = (const float*)d_in[6];
    float* out = (float*)d_out;

    cudaFuncSetAttribute(hmma_nt_kernel, cudaFuncAttributeMaxDynamicSharedMemorySize, SMEMB);
    cudaFuncSetAttribute(hmma_nt64_kernel, cudaFuncAttributeMaxDynamicSharedMemorySize, SMEMB64);

    float *biasb, *fb, *zsum;
    __half *Wh, *xTh, *xh, *ekh, *kxh, *ctxh, *Mh, *Eh, *wqTh, *pwh;
    cudaGetSymbolAddress((void**)&biasb, g_biasb);
    cudaGetSymbolAddress((void**)&fb, g_fb);
    cudaGetSymbolAddress((void**)&zsum, g_zsum);
    cudaGetSymbolAddress((void**)&Wh, g_Wh);
    cudaGetSymbolAddress((void**)&xTh, g_xTh);
    cudaGetSymbolAddress((void**)&xh, g_xh);
    cudaGetSymbolAddress((void**)&ekh, g_ekh);
    cudaGetSymbolAddress((void**)&kxh, g_kxh);
    cudaGetSymbolAddress((void**)&ctxh, g_ctxh);
    cudaGetSymbolAddress((void**)&Mh, g_Mh);
    cudaGetSymbolAddress((void**)&Eh, g_Eh);
    cudaGetSymbolAddress((void**)&wqTh, g_wqTh);
    cudaGetSymbolAddress((void**)&pwh, g_pwh);

    // 1) proj_w convert (+stats/zsum zero, +fb seed), fused x convert/
    //    transpose/stats, weight folding (stats inline), q-slab transpose
    f2h_init_kernel<<<(C_ * C_ / 4 + 255) / 256, 256>>>(proj_w, pwh, C_ * C_ / 4, proj_b);
    tconv_gn_kernel<<<dim3(N_ / 64, G_, B_), 256>>>(x, xTh, xh);
    prep_w_kernel<<<O3, 256>>>(qkv_w, qkv_b, gn_scale, gn_bias);
    wqt_kernel<<<dim3(C_ / 64, C_ / 64, B_), 256>>>();
    // 2) ek = exp(Wk . xT + bk), zsum = row sums  — persistent, fused softmax
    hmma_nt_kernel<<<NSM_SLOTS, 128, SMEMB>>>(
        Wh + (size_t)C_ * C_, C_, (size_t)O3 * C_,
        xTh, C_, (size_t)N_ * C_,
        nullptr, ekh, N_, (size_t)C_ * N_,
        biasb + C_, 1, O3, nullptr, 0, zsum, C_,
        N_ / 128, C_ / 128);
    // 3) kx[d,c] = (1/Z_d) * ek . x^T   (K=4096; row-divide in epilogue)
    hmma_nt64_kernel<<<dim3(C_ / 64, C_ / 64, B_), 128, SMEMB64>>>(
        ekh, N_, (size_t)C_ * N_,
        xh, N_, (size_t)C_ * N_,
        kxh, C_, (size_t)C_ * C_,
        nullptr, 0, 0, nullptr, 0, nullptr, zsum, N_);
    // 4) ctx[d,e] = kx . Wv^T + bv[e]
    hmma_nt64_kernel<<<dim3(C_ / 64, C_ / 64, B_), 128, SMEMB64>>>(
        kxh, C_, (size_t)C_ * C_,
        Wh + (size_t)2 * C_ * C_, C_, (size_t)O3 * C_,
        ctxh, C_, (size_t)C_ * C_,
        biasb + 2 * C_, 2, O3, nullptr, 0, nullptr, nullptr, C_);
    // 5) M[o,d] = proj_w . ctx^T   (+ fused fb += M @ bq via atomics)
    hmma_nt64_kernel<<<dim3(C_ / 64, C_ / 64, B_), 128, SMEMB64>>>(
        pwh, C_, 0,
        ctxh, C_, (size_t)C_ * C_,
        Mh, C_, (size_t)C_ * C_,
        nullptr, 0, 0, biasb, O3, fb, nullptr, C_);
    // 6) E[o,c] = M . WqT^T  (= M @ Wq)
    hmma_nt64_kernel<<<dim3(C_ / 64, C_ / 64, B_), 128, SMEMB64>>>(
        Mh, C_, (size_t)C_ * C_,
        wqTh, C_, (size_t)C_ * C_,
        Eh, C_, (size_t)C_ * C_,
        nullptr, 0, 0, nullptr, 0, nullptr, nullptr, C_);
    // 7) out[o,n] = E . xT^T + fb[o] + x — persistent
    hmma_nt_kernel<<<NSM_SLOTS, 128, SMEMB>>>(
        Eh, C_, (size_t)C_ * C_,
        xTh, C_, (size_t)N_ * C_,
        out, nullptr, N_, (size_t)C_ * N_,
        fb, 1, C_, x, (size_t)C_ * N_, nullptr, C_,
        N_ / 128, C_ / 128);
}